// round 1
// baseline (speedup 1.0000x reference)
#include <cuda_runtime.h>

// Problem constants
#define B_    32
#define S_    256
#define D_    1024
#define H_    16      // chunk (effective head) dim
#define C_    64      // number of chunks
#define MTOT  (B_ * S_)   // 8192

// Scratch for Q, K, V projections (allocation-free rule: device globals)
__device__ __align__(16) float g_q[MTOT * D_];
__device__ __align__(16) float g_k[MTOT * D_];
__device__ __align__(16) float g_v[MTOT * D_];

// ---------------------------------------------------------------------------
// Kernel 1: QKV projection.  O[m][n] = sum_k X[m][k] * W[n][k]
// 128x128 block tile, BK=16, 8x8 per-thread register tile, 256 threads.
// grid = (N/128, M/128, 3) ; z selects Wq/Wk/Wv -> g_q/g_k/g_v
// ---------------------------------------------------------------------------
#define BM 128
#define BN 128
#define BK 16

__global__ __launch_bounds__(256)
void qkv_gemm(const float* __restrict__ X,
              const float* __restrict__ Wq,
              const float* __restrict__ Wk,
              const float* __restrict__ Wv)
{
    __shared__ float As[BK][BM];   // transposed: As[k][m]
    __shared__ float Bs[BK][BN];   // transposed: Bs[k][n]

    const int z = blockIdx.z;
    const float* __restrict__ W = (z == 0) ? Wq : (z == 1) ? Wk : Wv;
    float* O = (z == 0) ? g_q : (z == 1) ? g_k : g_v;

    const int m0 = blockIdx.y * BM;
    const int n0 = blockIdx.x * BN;

    const int tid  = threadIdx.x;
    const int lrow = tid >> 2;          // 0..63
    const int lc4  = (tid & 3) << 2;    // 0,4,8,12

    const int ty = tid >> 4;            // 0..15
    const int tx = tid & 15;            // 0..15

    float acc[8][8];
#pragma unroll
    for (int i = 0; i < 8; i++)
#pragma unroll
        for (int j = 0; j < 8; j++) acc[i][j] = 0.0f;

    const float* Xp = X + (long)(m0 + lrow) * D_ + lc4;
    const float* Wp = W + (long)(n0 + lrow) * D_ + lc4;

    for (int k0 = 0; k0 < D_; k0 += BK) {
#pragma unroll
        for (int r = 0; r < 2; r++) {
            const int row = lrow + r * 64;
            float4 a = *(const float4*)(Xp + k0 + (long)r * 64 * D_);
            As[lc4 + 0][row] = a.x; As[lc4 + 1][row] = a.y;
            As[lc4 + 2][row] = a.z; As[lc4 + 3][row] = a.w;
            float4 b = *(const float4*)(Wp + k0 + (long)r * 64 * D_);
            Bs[lc4 + 0][row] = b.x; Bs[lc4 + 1][row] = b.y;
            Bs[lc4 + 2][row] = b.z; Bs[lc4 + 3][row] = b.w;
        }
        __syncthreads();

#pragma unroll
        for (int kk = 0; kk < BK; kk++) {
            float a[8], b[8];
#pragma unroll
            for (int i = 0; i < 8; i++) a[i] = As[kk][ty * 8 + i];
#pragma unroll
            for (int j = 0; j < 8; j++) b[j] = Bs[kk][tx * 8 + j];
#pragma unroll
            for (int i = 0; i < 8; i++)
#pragma unroll
                for (int j = 0; j < 8; j++)
                    acc[i][j] = fmaf(a[i], b[j], acc[i][j]);
        }
        __syncthreads();
    }

#pragma unroll
    for (int i = 0; i < 8; i++) {
        float* orow = O + (long)(m0 + ty * 8 + i) * D_ + n0 + tx * 8;
#pragma unroll
        for (int j4 = 0; j4 < 2; j4++) {
            float4 v = make_float4(acc[i][j4 * 4 + 0], acc[i][j4 * 4 + 1],
                                   acc[i][j4 * 4 + 2], acc[i][j4 * 4 + 3]);
            *(float4*)(orow + j4 * 4) = v;
        }
    }
}

// ---------------------------------------------------------------------------
// Pure-FMA exp: exp(x) for x <= 0 (softmax weights). Avoids MUFU (rt=8/SMSP
// would make 134M exps the bottleneck). ~1e-7 relative accuracy.
// ---------------------------------------------------------------------------
__device__ __forceinline__ float fexp(float x)
{
    x = fmaxf(x, -87.0f);                       // exp(-87) ~ 1.6e-38 ~ 0
    const float y = x * 1.4426950408889634f;    // log2(e)
    const float magic = 12582912.0f;            // 1.5 * 2^23
    const float t = y + magic;
    const int   n = __float_as_int(t) - __float_as_int(magic); // round(y), n in [-126,0]
    const float f = y - (t - magic);            // f in [-0.5, 0.5]
    // 2^f, Taylor (ln2*f)^k/k!, degree 6
    float p =           1.5403530e-4f;
    p = fmaf(p, f, 1.3333558e-3f);
    p = fmaf(p, f, 9.6181291e-3f);
    p = fmaf(p, f, 5.5504109e-2f);
    p = fmaf(p, f, 2.4022651e-1f);
    p = fmaf(p, f, 6.9314718e-1f);
    p = fmaf(p, f, 1.0f);
    return p * __int_as_float((n + 127) << 23); // * 2^n
}

// ---------------------------------------------------------------------------
// Kernel 2: attention per (chunk c, batch b). block = 256 threads, one thread
// per query row. K/V tiles (256x16) staged in smem. Two-pass softmax.
// grid = (C_=64, B_=32)
// ---------------------------------------------------------------------------
__global__ __launch_bounds__(256)
void attn(const float* __restrict__ mask, float* __restrict__ out)
{
    __shared__ float k_s[S_][H_];
    __shared__ float v_s[S_][H_];
    __shared__ float m_s[S_];

    const int c = blockIdx.x;
    const int b = blockIdx.y;
    const int t = threadIdx.x;

    const long base = (long)(b * S_) * D_ + c * H_;

    // Stage K, V tiles (coalesced float4, conflict-free STS.128)
    {
        const int r0 = t >> 2;
        const int c4 = (t & 3) << 2;
#pragma unroll
        for (int p = 0; p < 4; p++) {
            const int row = p * 64 + r0;
            *(float4*)&k_s[row][c4] = *(const float4*)&g_k[base + (long)row * D_ + c4];
            *(float4*)&v_s[row][c4] = *(const float4*)&g_v[base + (long)row * D_ + c4];
        }
    }
    m_s[t] = mask[b * S_ + t];

    // Own query row into registers
    float q[16];
#pragma unroll
    for (int i = 0; i < 4; i++) {
        float4 qq = *(const float4*)&g_q[base + (long)t * D_ + i * 4];
        q[i * 4 + 0] = qq.x; q[i * 4 + 1] = qq.y;
        q[i * 4 + 2] = qq.z; q[i * 4 + 3] = qq.w;
    }
    __syncthreads();

    const float mq = m_s[t];
    const float scale = 0.03125f; // 1/sqrt(1024)

    // Pass 1: row max
    float mx = -3.0e38f;
    for (int kk = 0; kk < S_; kk++) {
        float d0 = 0.f, d1 = 0.f, d2 = 0.f, d3 = 0.f;
#pragma unroll
        for (int h = 0; h < 4; h++) {
            d0 = fmaf(q[h],      k_s[kk][h],      d0);
            d1 = fmaf(q[h + 4],  k_s[kk][h + 4],  d1);
            d2 = fmaf(q[h + 8],  k_s[kk][h + 8],  d2);
            d3 = fmaf(q[h + 12], k_s[kk][h + 12], d3);
        }
        const float d = (d0 + d1) + (d2 + d3);
        const float logit = (mq > 0.f && m_s[kk] > 0.f) ? d * scale : -1e9f;
        mx = fmaxf(mx, logit);
    }

    // Pass 2: exp / accumulate
    float s = 0.f;
    float o[16];
#pragma unroll
    for (int h = 0; h < 16; h++) o[h] = 0.f;

    for (int kk = 0; kk < S_; kk++) {
        float d0 = 0.f, d1 = 0.f, d2 = 0.f, d3 = 0.f;
#pragma unroll
        for (int h = 0; h < 4; h++) {
            d0 = fmaf(q[h],      k_s[kk][h],      d0);
            d1 = fmaf(q[h + 4],  k_s[kk][h + 4],  d1);
            d2 = fmaf(q[h + 8],  k_s[kk][h + 8],  d2);
            d3 = fmaf(q[h + 12], k_s[kk][h + 12], d3);
        }
        const float d = (d0 + d1) + (d2 + d3);
        const float logit = (mq > 0.f && m_s[kk] > 0.f) ? d * scale : -1e9f;
        const float w = fexp(logit - mx);
        s += w;
#pragma unroll
        for (int h = 0; h < 16; h++) o[h] = fmaf(w, v_s[kk][h], o[h]);
    }

    const float inv = 1.0f / s;
    float* op = out + base + (long)t * D_;
#pragma unroll
    for (int i = 0; i < 4; i++) {
        float4 v = make_float4(o[i * 4 + 0] * inv, o[i * 4 + 1] * inv,
                               o[i * 4 + 2] * inv, o[i * 4 + 3] * inv);
        *(float4*)(op + i * 4) = v;
    }
}

// ---------------------------------------------------------------------------
extern "C" void kernel_launch(void* const* d_in, const int* in_sizes, int n_in,
                              void* d_out, int out_size)
{
    const float* x    = (const float*)d_in[0];  // [32,256,1024]
    const float* mask = (const float*)d_in[1];  // [32,256]
    const float* Wq   = (const float*)d_in[2];  // [1024,1024]
    const float* Wk   = (const float*)d_in[3];
    const float* Wv   = (const float*)d_in[4];
    float* out = (float*)d_out;                 // [32,256,1024]

    dim3 g1(D_ / BN, MTOT / BM, 3);
    qkv_gemm<<<g1, 256>>>(x, Wq, Wk, Wv);

    dim3 g2(C_, B_);
    attn<<<g2, 256>>>(mask, out);
}

// round 3
// speedup vs baseline: 1.8227x; 1.8227x over previous
#include <cuda_runtime.h>
#include <cuda_bf16.h>
#include <cstdint>

// Problem constants
#define B_    32
#define S_    256
#define D_    1024
#define H_    16
#define C_    64
#define MTOT  (B_ * S_)   // 8192

// Scratch (allocation-free rule: device globals)
__device__ __align__(16) float g_q[MTOT * D_];
__device__ __align__(16) float g_k[MTOT * D_];
__device__ __align__(16) float g_v[MTOT * D_];
__device__ __align__(16) __nv_bfloat16 g_xh[MTOT * D_];
__device__ __align__(16) __nv_bfloat16 g_xl[MTOT * D_];
__device__ __align__(16) __nv_bfloat16 g_wh[3 * D_ * D_];
__device__ __align__(16) __nv_bfloat16 g_wl[3 * D_ * D_];

// ---------------------------------------------------------------------------
__device__ __forceinline__ uint32_t smem_u32(const void* p) {
    uint32_t a;
    asm("{ .reg .u64 t; cvta.to.shared.u64 t, %1; cvt.u32.u64 %0, t; }" : "=r"(a) : "l"(p));
    return a;
}

__device__ __forceinline__ void cpa16(uint32_t dst, const void* src) {
    asm volatile("cp.async.cg.shared.global [%0], [%1], 16;" :: "r"(dst), "l"(src));
}

__device__ __forceinline__ void ldsm_x4(uint32_t* r, uint32_t addr) {
    asm volatile("ldmatrix.sync.aligned.m8n8.x4.shared.b16 {%0,%1,%2,%3}, [%4];"
                 : "=r"(r[0]), "=r"(r[1]), "=r"(r[2]), "=r"(r[3]) : "r"(addr));
}
__device__ __forceinline__ void ldsm_x2(uint32_t* r, uint32_t addr) {
    asm volatile("ldmatrix.sync.aligned.m8n8.x2.shared.b16 {%0,%1}, [%2];"
                 : "=r"(r[0]), "=r"(r[1]) : "r"(addr));
}

__device__ __forceinline__ void mma16816(float* d, const uint32_t* a, const uint32_t* b) {
    asm volatile(
        "mma.sync.aligned.m16n8k16.row.col.f32.bf16.bf16.f32 "
        "{%0,%1,%2,%3}, {%4,%5,%6,%7}, {%8,%9}, {%0,%1,%2,%3};"
        : "+f"(d[0]), "+f"(d[1]), "+f"(d[2]), "+f"(d[3])
        : "r"(a[0]), "r"(a[1]), "r"(a[2]), "r"(a[3]), "r"(b[0]), "r"(b[1]));
}

// ---------------------------------------------------------------------------
// Kernel 0: fp32 -> (bf16 hi, bf16 lo) split
// ---------------------------------------------------------------------------
__global__ __launch_bounds__(256)
void cvt_split(const float* __restrict__ src, __nv_bfloat16* __restrict__ hi,
               __nv_bfloat16* __restrict__ lo, int n4)
{
    int i = blockIdx.x * blockDim.x + threadIdx.x;
    if (i >= n4) return;
    float4 v = ((const float4*)src)[i];
    float a[4] = {v.x, v.y, v.z, v.w};
    __nv_bfloat16 h[4], l[4];
#pragma unroll
    for (int j = 0; j < 4; j++) {
        h[j] = __float2bfloat16(a[j]);
        l[j] = __float2bfloat16(a[j] - __bfloat162float(h[j]));
    }
    ((uint2*)hi)[i] = *(uint2*)h;
    ((uint2*)lo)[i] = *(uint2*)l;
}

// ---------------------------------------------------------------------------
// Kernel 1: bf16x3 split GEMM via mma.sync (HMMA).
// O[m][n] = sum_k X[m][k] W[n][k], fp32-grade via hi/lo split, 3 passes.
// Block tile 128x128, BK=32, 256 threads (8 warps: 4M x 2N, warp tile 32x64).
// Double-buffered cp.async. Padded smem stride 40 bf16 (80B) -> conflict-free
// ldmatrix. grid = (8, 64, 3).
// ---------------------------------------------------------------------------
#define GTM 128
#define GTN 128
#define GTK 32
#define NCHUNK (D_ / GTK)            // 32
#define LDT 40                        // padded stride in elements
#define TILE_ELEMS (128 * LDT)        // per tile
#define TILE_BYTES (TILE_ELEMS * 2)   // 10240 B
#define STAGE_BYTES (4 * TILE_BYTES)  // Ah Al Bh Bl = 40960 B
#define GEMM_SMEM (2 * STAGE_BYTES)   // 81920 B

__device__ __forceinline__ void load_chunk(uint32_t buf,
    const __nv_bfloat16* __restrict__ Ah, const __nv_bfloat16* __restrict__ Al,
    const __nv_bfloat16* __restrict__ Bh, const __nv_bfloat16* __restrict__ Bl,
    int k0, int tid)
{
#pragma unroll
    for (int i = 0; i < 2; i++) {
        int idx = tid + (i << 8);     // 0..511
        int row = idx >> 2;           // 0..127
        int seg = idx & 3;            // 0..3 (16B segments of the 64B row)
        uint32_t so = (uint32_t)(row * (LDT * 2) + seg * 16);
        long go = (long)row * D_ + k0 + seg * 8;
        cpa16(buf + so,                  Ah + go);
        cpa16(buf + TILE_BYTES + so,     Al + go);
        cpa16(buf + 2 * TILE_BYTES + so, Bh + go);
        cpa16(buf + 3 * TILE_BYTES + so, Bl + go);
    }
}

__global__ __launch_bounds__(256)
void qkv_tc()
{
    extern __shared__ char smem[];
    const uint32_t sb = smem_u32(smem);
    const int tid = threadIdx.x;
    const int wid = tid >> 5;
    const int lid = tid & 31;

    const int n0 = blockIdx.x * GTN;
    const int m0 = blockIdx.y * GTM;
    const int z  = blockIdx.z;

    const __nv_bfloat16* Ah = g_xh + (long)m0 * D_;
    const __nv_bfloat16* Al = g_xl + (long)m0 * D_;
    const __nv_bfloat16* Bh = g_wh + (long)z * D_ * D_ + (long)n0 * D_;
    const __nv_bfloat16* Bl = g_wl + (long)z * D_ * D_ + (long)n0 * D_;
    float* O = (z == 0) ? g_q : (z == 1) ? g_k : g_v;

    const int warp_m = (wid & 3) * 32;   // 4 warps along M
    const int warp_n = (wid >> 2) * 64;  // 2 warps along N

    // ldmatrix per-lane element offsets (within a tile, element units)
    // A x4: matrices (rows0-7,k0) (rows8-15,k0) (rows0-7,k8) (rows8-15,k8)
    const int a_row = ((lid >> 3) & 1) * 8 + (lid & 7);
    const int a_col = (lid >> 4) * 8;
    // B x2: matrices (n0-7,k0) (n0-7,k8)
    const int b_row = lid & 7;
    const int b_col = ((lid >> 3) & 1) * 8;

    float acc[2][8][4];
#pragma unroll
    for (int mt = 0; mt < 2; mt++)
#pragma unroll
        for (int nt = 0; nt < 8; nt++)
#pragma unroll
            for (int r = 0; r < 4; r++) acc[mt][nt][r] = 0.f;

    load_chunk(sb, Ah, Al, Bh, Bl, 0, tid);
    asm volatile("cp.async.commit_group;" ::: "memory");

#pragma unroll 1
    for (int c = 0; c < NCHUNK; c++) {
        asm volatile("cp.async.wait_group 0;" ::: "memory");
        __syncthreads();

        if (c + 1 < NCHUNK) {
            load_chunk(sb + ((c + 1) & 1) * STAGE_BYTES, Ah, Al, Bh, Bl,
                       (c + 1) * GTK, tid);
            asm volatile("cp.async.commit_group;" ::: "memory");
        }

        const uint32_t st = sb + (c & 1) * STAGE_BYTES;
        const uint32_t tAh = st;
        const uint32_t tAl = st + TILE_BYTES;
        const uint32_t tBh = st + 2 * TILE_BYTES;
        const uint32_t tBl = st + 3 * TILE_BYTES;

#pragma unroll
        for (int ks = 0; ks < 2; ks++) {
            const int kc = ks * 16;
            uint32_t ah[2][4], al[2][4];
#pragma unroll
            for (int mt = 0; mt < 2; mt++) {
                const uint32_t off =
                    (uint32_t)((warp_m + mt * 16 + a_row) * LDT + kc + a_col) * 2;
                ldsm_x4(ah[mt], tAh + off);
                ldsm_x4(al[mt], tAl + off);
            }
            uint32_t bh[8][2], bl[8][2];
#pragma unroll
            for (int nt = 0; nt < 8; nt++) {
                const uint32_t off =
                    (uint32_t)((warp_n + nt * 8 + b_row) * LDT + kc + b_col) * 2;
                ldsm_x2(bh[nt], tBh + off);
                ldsm_x2(bl[nt], tBl + off);
            }
#pragma unroll
            for (int nt = 0; nt < 8; nt++)
#pragma unroll
                for (int mt = 0; mt < 2; mt++) {
                    mma16816(acc[mt][nt], ah[mt], bh[nt]);
                    mma16816(acc[mt][nt], ah[mt], bl[nt]);
                    mma16816(acc[mt][nt], al[mt], bh[nt]);
                }
        }
        __syncthreads();
    }

    // Epilogue: direct global float2 stores per accumulator pair
    const int er = lid >> 2;         // 0..7
    const int ec = (lid & 3) * 2;    // 0,2,4,6
#pragma unroll
    for (int mt = 0; mt < 2; mt++)
#pragma unroll
        for (int nt = 0; nt < 8; nt++) {
            float* p0 = O + (long)(m0 + warp_m + mt * 16 + er) * D_
                          + n0 + warp_n + nt * 8 + ec;
            float* p1 = p0 + 8 * D_;
            *(float2*)p0 = make_float2(acc[mt][nt][0], acc[mt][nt][1]);
            *(float2*)p1 = make_float2(acc[mt][nt][2], acc[mt][nt][3]);
        }
}

// ---------------------------------------------------------------------------
// Pure-FMA exp (avoids MUFU throughput wall)
// ---------------------------------------------------------------------------
__device__ __forceinline__ float fexp(float x)
{
    x = fmaxf(x, -87.0f);
    const float y = x * 1.4426950408889634f;
    const float magic = 12582912.0f;
    const float t = y + magic;
    const int   n = __float_as_int(t) - __float_as_int(magic);
    const float f = y - (t - magic);
    float p =           1.5403530e-4f;
    p = fmaf(p, f, 1.3333558e-3f);
    p = fmaf(p, f, 9.6181291e-3f);
    p = fmaf(p, f, 5.5504109e-2f);
    p = fmaf(p, f, 2.4022651e-1f);
    p = fmaf(p, f, 6.9314718e-1f);
    p = fmaf(p, f, 1.0f);
    return p * __int_as_float((n + 127) << 23);
}

// ---------------------------------------------------------------------------
// Kernel 2: attention per (chunk c, batch b). Unchanged from R1.
// ---------------------------------------------------------------------------
__global__ __launch_bounds__(256)
void attn(const float* __restrict__ mask, float* __restrict__ out)
{
    __shared__ float k_s[S_][H_];
    __shared__ float v_s[S_][H_];
    __shared__ float m_s[S_];

    const int c = blockIdx.x;
    const int b = blockIdx.y;
    const int t = threadIdx.x;

    const long base = (long)(b * S_) * D_ + c * H_;

    {
        const int r0 = t >> 2;
        const int c4 = (t & 3) << 2;
#pragma unroll
        for (int p = 0; p < 4; p++) {
            const int row = p * 64 + r0;
            *(float4*)&k_s[row][c4] = *(const float4*)&g_k[base + (long)row * D_ + c4];
            *(float4*)&v_s[row][c4] = *(const float4*)&g_v[base + (long)row * D_ + c4];
        }
    }
    m_s[t] = mask[b * S_ + t];

    float q[16];
#pragma unroll
    for (int i = 0; i < 4; i++) {
        float4 qq = *(const float4*)&g_q[base + (long)t * D_ + i * 4];
        q[i * 4 + 0] = qq.x; q[i * 4 + 1] = qq.y;
        q[i * 4 + 2] = qq.z; q[i * 4 + 3] = qq.w;
    }
    __syncthreads();

    const float mq = m_s[t];
    const float scale = 0.03125f;

    float mx = -3.0e38f;
    for (int kk = 0; kk < S_; kk++) {
        float d0 = 0.f, d1 = 0.f, d2 = 0.f, d3 = 0.f;
#pragma unroll
        for (int h = 0; h < 4; h++) {
            d0 = fmaf(q[h],      k_s[kk][h],      d0);
            d1 = fmaf(q[h + 4],  k_s[kk][h + 4],  d1);
            d2 = fmaf(q[h + 8],  k_s[kk][h + 8],  d2);
            d3 = fmaf(q[h + 12], k_s[kk][h + 12], d3);
        }
        const float d = (d0 + d1) + (d2 + d3);
        const float logit = (mq > 0.f && m_s[kk] > 0.f) ? d * scale : -1e9f;
        mx = fmaxf(mx, logit);
    }

    float s = 0.f;
    float o[16];
#pragma unroll
    for (int h = 0; h < 16; h++) o[h] = 0.f;

    for (int kk = 0; kk < S_; kk++) {
        float d0 = 0.f, d1 = 0.f, d2 = 0.f, d3 = 0.f;
#pragma unroll
        for (int h = 0; h < 4; h++) {
            d0 = fmaf(q[h],      k_s[kk][h],      d0);
            d1 = fmaf(q[h + 4],  k_s[kk][h + 4],  d1);
            d2 = fmaf(q[h + 8],  k_s[kk][h + 8],  d2);
            d3 = fmaf(q[h + 12], k_s[kk][h + 12], d3);
        }
        const float d = (d0 + d1) + (d2 + d3);
        const float logit = (mq > 0.f && m_s[kk] > 0.f) ? d * scale : -1e9f;
        const float w = fexp(logit - mx);
        s += w;
#pragma unroll
        for (int h = 0; h < 16; h++) o[h] = fmaf(w, v_s[kk][h], o[h]);
    }

    const float inv = 1.0f / s;
    float* op = out + base + (long)t * D_;
#pragma unroll
    for (int i = 0; i < 4; i++) {
        float4 v = make_float4(o[i * 4 + 0] * inv, o[i * 4 + 1] * inv,
                               o[i * 4 + 2] * inv, o[i * 4 + 3] * inv);
        *(float4*)(op + i * 4) = v;
    }
}

// ---------------------------------------------------------------------------
extern "C" void kernel_launch(void* const* d_in, const int* in_sizes, int n_in,
                              void* d_out, int out_size)
{
    const float* x    = (const float*)d_in[0];
    const float* mask = (const float*)d_in[1];
    const float* Wq   = (const float*)d_in[2];
    const float* Wk   = (const float*)d_in[3];
    const float* Wv   = (const float*)d_in[4];
    float* out = (float*)d_out;

    __nv_bfloat16 *xh, *xl, *wh, *wl;
    cudaGetSymbolAddress((void**)&xh, g_xh);
    cudaGetSymbolAddress((void**)&xl, g_xl);
    cudaGetSymbolAddress((void**)&wh, g_wh);
    cudaGetSymbolAddress((void**)&wl, g_wl);

    cvt_split<<<(MTOT * D_ / 4 + 255) / 256, 256>>>(x, xh, xl, MTOT * D_ / 4);
    cvt_split<<<(D_ * D_ / 4 + 255) / 256, 256>>>(Wq, wh,               wl,               D_ * D_ / 4);
    cvt_split<<<(D_ * D_ / 4 + 255) / 256, 256>>>(Wk, wh + D_ * D_,     wl + D_ * D_,     D_ * D_ / 4);
    cvt_split<<<(D_ * D_ / 4 + 255) / 256, 256>>>(Wv, wh + 2 * D_ * D_, wl + 2 * D_ * D_, D_ * D_ / 4);

    static bool attr_set = false;
    if (!attr_set) {
        cudaFuncSetAttribute(qkv_tc, cudaFuncAttributeMaxDynamicSharedMemorySize, GEMM_SMEM);
        attr_set = true;
    }

    dim3 g1(D_ / GTN, MTOT / GTM, 3);
    qkv_tc<<<g1, 256, GEMM_SMEM>>>();

    dim3 g2(C_, B_);
    attn<<<g2, 256>>>(mask, out);
}

// round 4
// speedup vs baseline: 2.2780x; 1.2498x over previous
#include <cuda_runtime.h>
#include <cuda_bf16.h>
#include <cstdint>

// Problem constants
#define B_    32
#define S_    256
#define D_    1024
#define H_    16
#define C_    64
#define MTOT  (B_ * S_)   // 8192

// Scratch (allocation-free rule: device globals)
__device__ __align__(16) float g_q[MTOT * D_];
__device__ __align__(16) float g_k[MTOT * D_];
__device__ __align__(16) float g_v[MTOT * D_];
__device__ __align__(16) __nv_bfloat16 g_xh[MTOT * D_];
__device__ __align__(16) __nv_bfloat16 g_xl[MTOT * D_];
__device__ __align__(16) __nv_bfloat16 g_wh[3 * D_ * D_];
__device__ __align__(16) __nv_bfloat16 g_wl[3 * D_ * D_];

// ---------------------------------------------------------------------------
__device__ __forceinline__ uint32_t smem_u32(const void* p) {
    uint32_t a;
    asm("{ .reg .u64 t; cvta.to.shared.u64 t, %1; cvt.u32.u64 %0, t; }" : "=r"(a) : "l"(p));
    return a;
}

__device__ __forceinline__ void cpa16(uint32_t dst, const void* src) {
    asm volatile("cp.async.cg.shared.global [%0], [%1], 16;" :: "r"(dst), "l"(src));
}

__device__ __forceinline__ void ldsm_x4(uint32_t* r, uint32_t addr) {
    asm volatile("ldmatrix.sync.aligned.m8n8.x4.shared.b16 {%0,%1,%2,%3}, [%4];"
                 : "=r"(r[0]), "=r"(r[1]), "=r"(r[2]), "=r"(r[3]) : "r"(addr));
}

__device__ __forceinline__ void mma16816(float* d, const uint32_t* a, const uint32_t* b) {
    asm volatile(
        "mma.sync.aligned.m16n8k16.row.col.f32.bf16.bf16.f32 "
        "{%0,%1,%2,%3}, {%4,%5,%6,%7}, {%8,%9}, {%0,%1,%2,%3};"
        : "+f"(d[0]), "+f"(d[1]), "+f"(d[2]), "+f"(d[3])
        : "r"(a[0]), "r"(a[1]), "r"(a[2]), "r"(a[3]), "r"(b[0]), "r"(b[1]));
}

// ---------------------------------------------------------------------------
// Kernel 0a: X fp32 -> (bf16 hi, lo)
// ---------------------------------------------------------------------------
__device__ __forceinline__ void split4(const float* src, __nv_bfloat16* hi,
                                       __nv_bfloat16* lo, int i)
{
    float4 v = ((const float4*)src)[i];
    float a[4] = {v.x, v.y, v.z, v.w};
    __nv_bfloat16 h[4], l[4];
#pragma unroll
    for (int j = 0; j < 4; j++) {
        h[j] = __float2bfloat16(a[j]);
        l[j] = __float2bfloat16(a[j] - __bfloat162float(h[j]));
    }
    ((uint2*)hi)[i] = *(uint2*)h;
    ((uint2*)lo)[i] = *(uint2*)l;
}

__global__ __launch_bounds__(256)
void cvt_x(const float* __restrict__ src, __nv_bfloat16* __restrict__ hi,
           __nv_bfloat16* __restrict__ lo, int n4)
{
    int i = blockIdx.x * blockDim.x + threadIdx.x;
    if (i < n4) split4(src, hi, lo, i);
}

// Kernel 0b: all three weights in one launch (grid.z selects)
__global__ __launch_bounds__(256)
void cvt_w(const float* __restrict__ Wq, const float* __restrict__ Wk,
           const float* __restrict__ Wv, __nv_bfloat16* __restrict__ hi,
           __nv_bfloat16* __restrict__ lo)
{
    const int z = blockIdx.z;
    const float* src = (z == 0) ? Wq : (z == 1) ? Wk : Wv;
    const int n4 = D_ * D_ / 4;
    int i = blockIdx.x * blockDim.x + threadIdx.x;
    if (i < n4) split4(src, hi + (long)z * D_ * D_, lo + (long)z * D_ * D_, i);
}

// ---------------------------------------------------------------------------
// Kernel 1: bf16x3 split GEMM via mma.sync (HMMA).
// Block tile 128x128, BK=32, 256 threads (8 warps: 4M x 2N, warp tile 32x64).
// 2 CTAs/SM, double-buffered cp.async, padded stride 40 (conflict-free LDSM).
// ---------------------------------------------------------------------------
#define GTM 128
#define GTN 128
#define GTK 32
#define NCHUNK (D_ / GTK)            // 32
#define LDT 40                        // padded stride in elements
#define TILE_BYTES (128 * LDT * 2)    // 10240 B
#define STAGE_BYTES (4 * TILE_BYTES)  // Ah Al Bh Bl = 40960 B
#define GEMM_SMEM (2 * STAGE_BYTES)   // 81920 B

__device__ __forceinline__ void load_chunk(uint32_t buf,
    const __nv_bfloat16* __restrict__ Ah, const __nv_bfloat16* __restrict__ Al,
    const __nv_bfloat16* __restrict__ Bh, const __nv_bfloat16* __restrict__ Bl,
    int k0, int tid)
{
#pragma unroll
    for (int i = 0; i < 2; i++) {
        int idx = tid + (i << 8);     // 0..511
        int row = idx >> 2;           // 0..127
        int seg = idx & 3;            // 16B segments of the 64B row
        uint32_t so = (uint32_t)(row * (LDT * 2) + seg * 16);
        long go = (long)row * D_ + k0 + seg * 8;
        cpa16(buf + so,                  Ah + go);
        cpa16(buf + TILE_BYTES + so,     Al + go);
        cpa16(buf + 2 * TILE_BYTES + so, Bh + go);
        cpa16(buf + 3 * TILE_BYTES + so, Bl + go);
    }
}

__global__ __launch_bounds__(256, 2)
void qkv_tc()
{
    extern __shared__ char smem[];
    const uint32_t sb = smem_u32(smem);
    const int tid = threadIdx.x;
    const int wid = tid >> 5;
    const int lid = tid & 31;

    const int n0 = blockIdx.x * GTN;
    const int m0 = blockIdx.y * GTM;
    const int z  = blockIdx.z;

    const __nv_bfloat16* Ah = g_xh + (long)m0 * D_;
    const __nv_bfloat16* Al = g_xl + (long)m0 * D_;
    const __nv_bfloat16* Bh = g_wh + (long)z * D_ * D_ + (long)n0 * D_;
    const __nv_bfloat16* Bl = g_wl + (long)z * D_ * D_ + (long)n0 * D_;
    float* O = (z == 0) ? g_q : (z == 1) ? g_k : g_v;

    const int warp_m = (wid & 3) * 32;   // 4 warps along M
    const int warp_n = (wid >> 2) * 64;  // 2 warps along N

    // A x4 lane mapping: matrices (m0-7,k0)(m8-15,k0)(m0-7,k8)(m8-15,k8)
    const int a_row = ((lid >> 3) & 1) * 8 + (lid & 7);
    const int a_col = (lid >> 4) * 8;
    // B x4 lane mapping: matrices (n,k0)(n,k8)(n+8,k0)(n+8,k8)
    const int mi    = lid >> 3;
    const int b_row = (mi >> 1) * 8 + (lid & 7);
    const int b_col = (mi & 1) * 8;

    float acc[2][8][4];
#pragma unroll
    for (int mt = 0; mt < 2; mt++)
#pragma unroll
        for (int nt = 0; nt < 8; nt++)
#pragma unroll
            for (int r = 0; r < 4; r++) acc[mt][nt][r] = 0.f;

    load_chunk(sb, Ah, Al, Bh, Bl, 0, tid);
    asm volatile("cp.async.commit_group;" ::: "memory");

#pragma unroll 1
    for (int c = 0; c < NCHUNK; c++) {
        asm volatile("cp.async.wait_group 0;" ::: "memory");
        __syncthreads();

        if (c + 1 < NCHUNK) {
            load_chunk(sb + ((c + 1) & 1) * STAGE_BYTES, Ah, Al, Bh, Bl,
                       (c + 1) * GTK, tid);
            asm volatile("cp.async.commit_group;" ::: "memory");
        }

        const uint32_t st = sb + (c & 1) * STAGE_BYTES;
        const uint32_t tAh = st;
        const uint32_t tAl = st + TILE_BYTES;
        const uint32_t tBh = st + 2 * TILE_BYTES;
        const uint32_t tBl = st + 3 * TILE_BYTES;

#pragma unroll
        for (int ks = 0; ks < 2; ks++) {
            const int kc = ks * 16;
            uint32_t ah[2][4], al[2][4];
#pragma unroll
            for (int mt = 0; mt < 2; mt++) {
                const uint32_t off =
                    (uint32_t)((warp_m + mt * 16 + a_row) * LDT + kc + a_col) * 2;
                ldsm_x4(ah[mt], tAh + off);
                ldsm_x4(al[mt], tAl + off);
            }
            // B: 4 pairs of n-tiles, each x4 covers (n..n+15) x (k0,k8)
            uint32_t bh[4][4], bl[4][4];
#pragma unroll
            for (int p = 0; p < 4; p++) {
                const uint32_t off =
                    (uint32_t)((warp_n + p * 16 + b_row) * LDT + kc + b_col) * 2;
                ldsm_x4(bh[p], tBh + off);
                ldsm_x4(bl[p], tBl + off);
            }
#pragma unroll
            for (int p = 0; p < 4; p++)
#pragma unroll
                for (int half = 0; half < 2; half++) {
                    const int nt = p * 2 + half;
#pragma unroll
                    for (int mt = 0; mt < 2; mt++) {
                        mma16816(acc[mt][nt], ah[mt], &bh[p][half * 2]);
                        mma16816(acc[mt][nt], ah[mt], &bl[p][half * 2]);
                        mma16816(acc[mt][nt], al[mt], &bh[p][half * 2]);
                    }
                }
        }
        __syncthreads();
    }

    // Epilogue: direct global float2 stores
    const int er = lid >> 2;
    const int ec = (lid & 3) * 2;
#pragma unroll
    for (int mt = 0; mt < 2; mt++)
#pragma unroll
        for (int nt = 0; nt < 8; nt++) {
            float* p0 = O + (long)(m0 + warp_m + mt * 16 + er) * D_
                          + n0 + warp_n + nt * 8 + ec;
            float* p1 = p0 + 8 * D_;
            *(float2*)p0 = make_float2(acc[mt][nt][0], acc[mt][nt][1]);
            *(float2*)p1 = make_float2(acc[mt][nt][2], acc[mt][nt][3]);
        }
}

// ---------------------------------------------------------------------------
// Pure-FMA exp (avoids MUFU throughput wall). Valid for x in [-87, 88].
// ---------------------------------------------------------------------------
__device__ __forceinline__ float fexp(float x)
{
    x = fmaxf(x, -87.0f);
    const float y = x * 1.4426950408889634f;
    const float magic = 12582912.0f;
    const float t = y + magic;
    const int   n = __float_as_int(t) - __float_as_int(magic);
    const float f = y - (t - magic);
    float p =           1.5403530e-4f;
    p = fmaf(p, f, 1.3333558e-3f);
    p = fmaf(p, f, 9.6181291e-3f);
    p = fmaf(p, f, 5.5504109e-2f);
    p = fmaf(p, f, 2.4022651e-1f);
    p = fmaf(p, f, 6.9314718e-1f);
    p = fmaf(p, f, 1.0f);
    return p * __int_as_float((n + 127) << 23);
}

// ---------------------------------------------------------------------------
// Kernel 2: attention per (chunk c, batch b). SINGLE-PASS softmax (no max
// subtraction — logits bounded; softmax is shift-invariant; masked entries
// produce e^-87 which reproduces the uniform-average degenerate case).
// ---------------------------------------------------------------------------
__global__ __launch_bounds__(256)
void attn(const float* __restrict__ mask, float* __restrict__ out)
{
    __shared__ float k_s[S_][H_];
    __shared__ float v_s[S_][H_];
    __shared__ float m_s[S_];

    const int c = blockIdx.x;
    const int b = blockIdx.y;
    const int t = threadIdx.x;

    const long base = (long)(b * S_) * D_ + c * H_;

    {
        const int r0 = t >> 2;
        const int c4 = (t & 3) << 2;
#pragma unroll
        for (int p = 0; p < 4; p++) {
            const int row = p * 64 + r0;
            *(float4*)&k_s[row][c4] = *(const float4*)&g_k[base + (long)row * D_ + c4];
            *(float4*)&v_s[row][c4] = *(const float4*)&g_v[base + (long)row * D_ + c4];
        }
    }
    m_s[t] = mask[b * S_ + t];

    float q[16];
#pragma unroll
    for (int i = 0; i < 4; i++) {
        float4 qq = *(const float4*)&g_q[base + (long)t * D_ + i * 4];
        q[i * 4 + 0] = qq.x; q[i * 4 + 1] = qq.y;
        q[i * 4 + 2] = qq.z; q[i * 4 + 3] = qq.w;
    }
    __syncthreads();

    const float mq = m_s[t];
    const float scale = 0.03125f; // 1/sqrt(1024)

    float s = 0.f;
    float o[16];
#pragma unroll
    for (int h = 0; h < 16; h++) o[h] = 0.f;

#pragma unroll 2
    for (int kk = 0; kk < S_; kk++) {
        float d0 = 0.f, d1 = 0.f, d2 = 0.f, d3 = 0.f;
#pragma unroll
        for (int h = 0; h < 4; h++) {
            d0 = fmaf(q[h],      k_s[kk][h],      d0);
            d1 = fmaf(q[h + 4],  k_s[kk][h + 4],  d1);
            d2 = fmaf(q[h + 8],  k_s[kk][h + 8],  d2);
            d3 = fmaf(q[h + 12], k_s[kk][h + 12], d3);
        }
        const float d = (d0 + d1) + (d2 + d3);
        const float logit = (mq > 0.f && m_s[kk] > 0.f) ? d * scale : -1e9f;
        const float w = fexp(logit);
        s += w;
#pragma unroll
        for (int h = 0; h < 16; h++) o[h] = fmaf(w, v_s[kk][h], o[h]);
    }

    const float inv = 1.0f / s;
    float* op = out + base + (long)t * D_;
#pragma unroll
    for (int i = 0; i < 4; i++) {
        float4 v = make_float4(o[i * 4 + 0] * inv, o[i * 4 + 1] * inv,
                               o[i * 4 + 2] * inv, o[i * 4 + 3] * inv);
        *(float4*)(op + i * 4) = v;
    }
}

// ---------------------------------------------------------------------------
extern "C" void kernel_launch(void* const* d_in, const int* in_sizes, int n_in,
                              void* d_out, int out_size)
{
    const float* x    = (const float*)d_in[0];
    const float* mask = (const float*)d_in[1];
    const float* Wq   = (const float*)d_in[2];
    const float* Wk   = (const float*)d_in[3];
    const float* Wv   = (const float*)d_in[4];
    float* out = (float*)d_out;

    __nv_bfloat16 *xh, *xl, *wh, *wl;
    cudaGetSymbolAddress((void**)&xh, g_xh);
    cudaGetSymbolAddress((void**)&xl, g_xl);
    cudaGetSymbolAddress((void**)&wh, g_wh);
    cudaGetSymbolAddress((void**)&wl, g_wl);

    cvt_x<<<(MTOT * D_ / 4 + 255) / 256, 256>>>(x, xh, xl, MTOT * D_ / 4);
    dim3 gw((D_ * D_ / 4 + 255) / 256, 1, 3);
    cvt_w<<<gw, 256>>>(Wq, Wk, Wv, wh, wl);

    static bool attr_set = false;
    if (!attr_set) {
        cudaFuncSetAttribute(qkv_tc, cudaFuncAttributeMaxDynamicSharedMemorySize, GEMM_SMEM);
        attr_set = true;
    }

    dim3 g1(D_ / GTN, MTOT / GTM, 3);
    qkv_tc<<<g1, 256, GEMM_SMEM>>>();

    dim3 g2(C_, B_);
    attn<<<g2, 256>>>(mask, out);
}

// round 5
// speedup vs baseline: 2.5149x; 1.1040x over previous
#include <cuda_runtime.h>
#include <cuda_bf16.h>
#include <cstdint>

// Problem constants
#define B_    32
#define S_    256
#define D_    1024
#define H_    16
#define C_    64
#define MTOT  (B_ * S_)   // 8192

typedef unsigned long long u64t;

// Scratch (allocation-free rule: device globals)
__device__ __align__(16) float g_q[MTOT * D_];
__device__ __align__(16) float g_k[MTOT * D_];
__device__ __align__(16) float g_v[MTOT * D_];
__device__ __align__(16) __nv_bfloat16 g_xh[MTOT * D_];
__device__ __align__(16) __nv_bfloat16 g_xl[MTOT * D_];
__device__ __align__(16) __nv_bfloat16 g_wh[3 * D_ * D_];
__device__ __align__(16) __nv_bfloat16 g_wl[3 * D_ * D_];

// ---------------------------------------------------------------------------
__device__ __forceinline__ uint32_t smem_u32(const void* p) {
    uint32_t a;
    asm("{ .reg .u64 t; cvta.to.shared.u64 t, %1; cvt.u32.u64 %0, t; }" : "=r"(a) : "l"(p));
    return a;
}

__device__ __forceinline__ void cpa16(uint32_t dst, const void* src) {
    asm volatile("cp.async.cg.shared.global [%0], [%1], 16;" :: "r"(dst), "l"(src));
}

__device__ __forceinline__ void ldsm_x4(uint32_t* r, uint32_t addr) {
    asm volatile("ldmatrix.sync.aligned.m8n8.x4.shared.b16 {%0,%1,%2,%3}, [%4];"
                 : "=r"(r[0]), "=r"(r[1]), "=r"(r[2]), "=r"(r[3]) : "r"(addr));
}

__device__ __forceinline__ void mma16816(float* d, const uint32_t* a, const uint32_t* b) {
    asm volatile(
        "mma.sync.aligned.m16n8k16.row.col.f32.bf16.bf16.f32 "
        "{%0,%1,%2,%3}, {%4,%5,%6,%7}, {%8,%9}, {%0,%1,%2,%3};"
        : "+f"(d[0]), "+f"(d[1]), "+f"(d[2]), "+f"(d[3])
        : "r"(a[0]), "r"(a[1]), "r"(a[2]), "r"(a[3]), "r"(b[0]), "r"(b[1]));
}

// Packed f32x2 ops (sm_100+ base ISA)
__device__ __forceinline__ u64t fma2(u64t a, u64t b, u64t c) {
    u64t d;
    asm("fma.rn.f32x2 %0, %1, %2, %3;" : "=l"(d) : "l"(a), "l"(b), "l"(c));
    return d;
}
__device__ __forceinline__ u64t add2(u64t a, u64t b) {
    u64t d;
    asm("add.rn.f32x2 %0, %1, %2;" : "=l"(d) : "l"(a), "l"(b));
    return d;
}
__device__ __forceinline__ u64t pack2(float lo, float hi) {
    u64t d;
    asm("mov.b64 %0, {%1, %2};" : "=l"(d) : "f"(lo), "f"(hi));
    return d;
}
__device__ __forceinline__ void unpack2(u64t v, float& a, float& b) {
    asm("mov.b64 {%0, %1}, %2;" : "=f"(a), "=f"(b) : "l"(v));
}
__device__ __forceinline__ float ex2f(float x) {
    float r;
    asm("ex2.approx.f32 %0, %1;" : "=f"(r) : "f"(x));
    return r;
}
__device__ __forceinline__ float rcpf(float x) {
    float r;
    asm("rcp.approx.f32 %0, %1;" : "=f"(r) : "f"(x));
    return r;
}

// ---------------------------------------------------------------------------
// Kernel 0: fp32 -> (bf16 hi, lo) split
// ---------------------------------------------------------------------------
__device__ __forceinline__ void split4(const float* src, __nv_bfloat16* hi,
                                       __nv_bfloat16* lo, int i)
{
    float4 v = ((const float4*)src)[i];
    float a[4] = {v.x, v.y, v.z, v.w};
    __nv_bfloat16 h[4], l[4];
#pragma unroll
    for (int j = 0; j < 4; j++) {
        h[j] = __float2bfloat16(a[j]);
        l[j] = __float2bfloat16(a[j] - __bfloat162float(h[j]));
    }
    ((uint2*)hi)[i] = *(uint2*)h;
    ((uint2*)lo)[i] = *(uint2*)l;
}

__global__ __launch_bounds__(256)
void cvt_x(const float* __restrict__ src, __nv_bfloat16* __restrict__ hi,
           __nv_bfloat16* __restrict__ lo, int n4)
{
    int i = blockIdx.x * blockDim.x + threadIdx.x;
    if (i < n4) split4(src, hi, lo, i);
}

__global__ __launch_bounds__(256)
void cvt_w(const float* __restrict__ Wq, const float* __restrict__ Wk,
           const float* __restrict__ Wv, __nv_bfloat16* __restrict__ hi,
           __nv_bfloat16* __restrict__ lo)
{
    const int z = blockIdx.z;
    const float* src = (z == 0) ? Wq : (z == 1) ? Wk : Wv;
    const int n4 = D_ * D_ / 4;
    int i = blockIdx.x * blockDim.x + threadIdx.x;
    if (i < n4) split4(src, hi + (long)z * D_ * D_, lo + (long)z * D_ * D_, i);
}

// ---------------------------------------------------------------------------
// Kernel 1: bf16x3 split GEMM via mma.sync (HMMA).
// Block tile 128x128, BK=32, 256 threads (8 warps: 4M x 2N, warp tile 32x64).
// 2 CTAs/SM. B-fragments loaded per n-pair (lower reg pressure), term-major
// MMA order (same-acc dependency distance 4).
// ---------------------------------------------------------------------------
#define GTM 128
#define GTN 128
#define GTK 32
#define NCHUNK (D_ / GTK)            // 32
#define LDT 40                        // padded stride in elements
#define TILE_BYTES (128 * LDT * 2)    // 10240 B
#define STAGE_BYTES (4 * TILE_BYTES)  // Ah Al Bh Bl = 40960 B
#define GEMM_SMEM (2 * STAGE_BYTES)   // 81920 B

__device__ __forceinline__ void load_chunk(uint32_t buf,
    const __nv_bfloat16* __restrict__ Ah, const __nv_bfloat16* __restrict__ Al,
    const __nv_bfloat16* __restrict__ Bh, const __nv_bfloat16* __restrict__ Bl,
    int k0, int tid)
{
#pragma unroll
    for (int i = 0; i < 2; i++) {
        int idx = tid + (i << 8);
        int row = idx >> 2;
        int seg = idx & 3;
        uint32_t so = (uint32_t)(row * (LDT * 2) + seg * 16);
        long go = (long)row * D_ + k0 + seg * 8;
        cpa16(buf + so,                  Ah + go);
        cpa16(buf + TILE_BYTES + so,     Al + go);
        cpa16(buf + 2 * TILE_BYTES + so, Bh + go);
        cpa16(buf + 3 * TILE_BYTES + so, Bl + go);
    }
}

__global__ __launch_bounds__(256, 2)
void qkv_tc()
{
    extern __shared__ char smem[];
    const uint32_t sb = smem_u32(smem);
    const int tid = threadIdx.x;
    const int wid = tid >> 5;
    const int lid = tid & 31;

    const int n0 = blockIdx.x * GTN;
    const int m0 = blockIdx.y * GTM;
    const int z  = blockIdx.z;

    const __nv_bfloat16* Ah = g_xh + (long)m0 * D_;
    const __nv_bfloat16* Al = g_xl + (long)m0 * D_;
    const __nv_bfloat16* Bh = g_wh + (long)z * D_ * D_ + (long)n0 * D_;
    const __nv_bfloat16* Bl = g_wl + (long)z * D_ * D_ + (long)n0 * D_;
    float* O = (z == 0) ? g_q : (z == 1) ? g_k : g_v;

    const int warp_m = (wid & 3) * 32;
    const int warp_n = (wid >> 2) * 64;

    const int a_row = ((lid >> 3) & 1) * 8 + (lid & 7);
    const int a_col = (lid >> 4) * 8;
    const int mi    = lid >> 3;
    const int b_row = (mi >> 1) * 8 + (lid & 7);
    const int b_col = (mi & 1) * 8;

    float acc[2][8][4];
#pragma unroll
    for (int mt = 0; mt < 2; mt++)
#pragma unroll
        for (int nt = 0; nt < 8; nt++)
#pragma unroll
            for (int r = 0; r < 4; r++) acc[mt][nt][r] = 0.f;

    load_chunk(sb, Ah, Al, Bh, Bl, 0, tid);
    asm volatile("cp.async.commit_group;" ::: "memory");

#pragma unroll 1
    for (int c = 0; c < NCHUNK; c++) {
        asm volatile("cp.async.wait_group 0;" ::: "memory");
        __syncthreads();

        if (c + 1 < NCHUNK) {
            load_chunk(sb + ((c + 1) & 1) * STAGE_BYTES, Ah, Al, Bh, Bl,
                       (c + 1) * GTK, tid);
            asm volatile("cp.async.commit_group;" ::: "memory");
        }

        const uint32_t st = sb + (c & 1) * STAGE_BYTES;
        const uint32_t tAh = st;
        const uint32_t tAl = st + TILE_BYTES;
        const uint32_t tBh = st + 2 * TILE_BYTES;
        const uint32_t tBl = st + 3 * TILE_BYTES;

#pragma unroll
        for (int ks = 0; ks < 2; ks++) {
            const int kc = ks * 16;
            uint32_t ah[2][4], al[2][4];
#pragma unroll
            for (int mt = 0; mt < 2; mt++) {
                const uint32_t off =
                    (uint32_t)((warp_m + mt * 16 + a_row) * LDT + kc + a_col) * 2;
                ldsm_x4(ah[mt], tAh + off);
                ldsm_x4(al[mt], tAl + off);
            }
#pragma unroll
            for (int p = 0; p < 4; p++) {
                const uint32_t off =
                    (uint32_t)((warp_n + p * 16 + b_row) * LDT + kc + b_col) * 2;
                uint32_t bh[4], bl[4];
                ldsm_x4(bh, tBh + off);
                ldsm_x4(bl, tBl + off);
                // term-major: same-acc dependency distance = 4 MMAs
#pragma unroll
                for (int half = 0; half < 2; half++)
#pragma unroll
                    for (int mt = 0; mt < 2; mt++)
                        mma16816(acc[mt][p * 2 + half], ah[mt], &bh[half * 2]);
#pragma unroll
                for (int half = 0; half < 2; half++)
#pragma unroll
                    for (int mt = 0; mt < 2; mt++)
                        mma16816(acc[mt][p * 2 + half], ah[mt], &bl[half * 2]);
#pragma unroll
                for (int half = 0; half < 2; half++)
#pragma unroll
                    for (int mt = 0; mt < 2; mt++)
                        mma16816(acc[mt][p * 2 + half], al[mt], &bh[half * 2]);
            }
        }
        __syncthreads();
    }

    const int er = lid >> 2;
    const int ec = (lid & 3) * 2;
#pragma unroll
    for (int mt = 0; mt < 2; mt++)
#pragma unroll
        for (int nt = 0; nt < 8; nt++) {
            float* p0 = O + (long)(m0 + warp_m + mt * 16 + er) * D_
                          + n0 + warp_n + nt * 8 + ec;
            float* p1 = p0 + 8 * D_;
            *(float2*)p0 = make_float2(acc[mt][nt][0], acc[mt][nt][1]);
            *(float2*)p1 = make_float2(acc[mt][nt][2], acc[mt][nt][3]);
        }
}

// ---------------------------------------------------------------------------
// Kernel 2: attention per (chunk c, batch b). Single-pass softmax in log2
// domain: w = ex2(d * scale*log2e), masked -> ex2(-100) ~ 7.9e-31.
// Packed f32x2 FMA for the 16-dim dot and 16-dim V accumulation.
// ---------------------------------------------------------------------------
__global__ __launch_bounds__(256)
void attn(const float* __restrict__ mask, float* __restrict__ out)
{
    __shared__ float k_s[S_][H_];
    __shared__ float v_s[S_][H_];
    __shared__ float m_s[S_];   // 1.0 if key unmasked else 0.0

    const int c = blockIdx.x;
    const int b = blockIdx.y;
    const int t = threadIdx.x;

    const long base = (long)(b * S_) * D_ + c * H_;

    {
        const int r0 = t >> 2;
        const int c4 = (t & 3) << 2;
#pragma unroll
        for (int p = 0; p < 4; p++) {
            const int row = p * 64 + r0;
            *(float4*)&k_s[row][c4] = *(const float4*)&g_k[base + (long)row * D_ + c4];
            *(float4*)&v_s[row][c4] = *(const float4*)&g_v[base + (long)row * D_ + c4];
        }
    }
    const float mq_raw = mask[b * S_ + t];
    m_s[t] = (mq_raw > 0.f) ? 1.0f : 0.0f;

    // own query row, packed as 8 f32x2
    u64t q2[8];
#pragma unroll
    for (int i = 0; i < 4; i++) {
        ulonglong2 qq = *(const ulonglong2*)&g_q[base + (long)t * D_ + i * 4];
        q2[i * 2 + 0] = qq.x;
        q2[i * 2 + 1] = qq.y;
    }
    __syncthreads();

    // scale2 = log2(e)/sqrt(1024); 0 if own row masked (-> uniform weights)
    const float scale2 = (mq_raw > 0.f) ? (1.4426950408889634f * 0.03125f) : 0.0f;

    float s = 0.f;
    u64t o2[8];
#pragma unroll
    for (int h = 0; h < 8; h++) o2[h] = 0ull;

#pragma unroll 4
    for (int kk = 0; kk < S_; kk++) {
        const ulonglong2 ka = *(const ulonglong2*)&k_s[kk][0];
        const ulonglong2 kb = *(const ulonglong2*)&k_s[kk][4];
        const ulonglong2 kc = *(const ulonglong2*)&k_s[kk][8];
        const ulonglong2 kd = *(const ulonglong2*)&k_s[kk][12];

        u64t da = fma2(q2[0], ka.x, 0ull);
        u64t db = fma2(q2[1], ka.y, 0ull);
        da = fma2(q2[2], kb.x, da);
        db = fma2(q2[3], kb.y, db);
        da = fma2(q2[4], kc.x, da);
        db = fma2(q2[5], kc.y, db);
        da = fma2(q2[6], kd.x, da);
        db = fma2(q2[7], kd.y, db);
        const u64t dd = add2(da, db);
        float f0, f1;
        unpack2(dd, f0, f1);
        const float d = f0 + f1;

        // masked: l2 = -100 -> weight ~7.9e-31 (>0, degenerates to uniform avg)
        const float l2 = fmaf(m_s[kk], fmaf(d, scale2, 100.f), -100.f);
        const float w = ex2f(l2);
        s += w;

        const u64t w2 = pack2(w, w);
        const ulonglong2 va = *(const ulonglong2*)&v_s[kk][0];
        const ulonglong2 vb = *(const ulonglong2*)&v_s[kk][4];
        const ulonglong2 vc = *(const ulonglong2*)&v_s[kk][8];
        const ulonglong2 vd = *(const ulonglong2*)&v_s[kk][12];
        o2[0] = fma2(w2, va.x, o2[0]);
        o2[1] = fma2(w2, va.y, o2[1]);
        o2[2] = fma2(w2, vb.x, o2[2]);
        o2[3] = fma2(w2, vb.y, o2[3]);
        o2[4] = fma2(w2, vc.x, o2[4]);
        o2[5] = fma2(w2, vc.y, o2[5]);
        o2[6] = fma2(w2, vd.x, o2[6]);
        o2[7] = fma2(w2, vd.y, o2[7]);
    }

    const float inv = rcpf(s);
    float* op = out + base + (long)t * D_;
#pragma unroll
    for (int i = 0; i < 4; i++) {
        float a0, a1, a2, a3;
        unpack2(o2[i * 2 + 0], a0, a1);
        unpack2(o2[i * 2 + 1], a2, a3);
        float4 v = make_float4(a0 * inv, a1 * inv, a2 * inv, a3 * inv);
        *(float4*)(op + i * 4) = v;
    }
}

// ---------------------------------------------------------------------------
extern "C" void kernel_launch(void* const* d_in, const int* in_sizes, int n_in,
                              void* d_out, int out_size)
{
    const float* x    = (const float*)d_in[0];
    const float* mask = (const float*)d_in[1];
    const float* Wq   = (const float*)d_in[2];
    const float* Wk   = (const float*)d_in[3];
    const float* Wv   = (const float*)d_in[4];
    float* out = (float*)d_out;

    __nv_bfloat16 *xh, *xl, *wh, *wl;
    cudaGetSymbolAddress((void**)&xh, g_xh);
    cudaGetSymbolAddress((void**)&xl, g_xl);
    cudaGetSymbolAddress((void**)&wh, g_wh);
    cudaGetSymbolAddress((void**)&wl, g_wl);

    cvt_x<<<(MTOT * D_ / 4 + 255) / 256, 256>>>(x, xh, xl, MTOT * D_ / 4);
    dim3 gw((D_ * D_ / 4 + 255) / 256, 1, 3);
    cvt_w<<<gw, 256>>>(Wq, Wk, Wv, wh, wl);

    static bool attr_set = false;
    if (!attr_set) {
        cudaFuncSetAttribute(qkv_tc, cudaFuncAttributeMaxDynamicSharedMemorySize, GEMM_SMEM);
        attr_set = true;
    }

    dim3 g1(D_ / GTN, MTOT / GTM, 3);
    qkv_tc<<<g1, 256, GEMM_SMEM>>>();

    dim3 g2(C_, B_);
    attn<<<g2, 256>>>(mask, out);
}

// round 7
// speedup vs baseline: 3.1070x; 1.2355x over previous
#include <cuda_runtime.h>
#include <cuda_fp16.h>
#include <cstdint>

// Problem constants
#define B_    32
#define S_    256
#define D_    1024
#define H_    16
#define C_    64
#define MTOT  (B_ * S_)   // 8192

typedef unsigned long long u64t;

// Scratch (allocation-free rule: device globals)
__device__ __align__(16) float g_q[MTOT * D_];
__device__ __align__(16) float g_k[MTOT * D_];
__device__ __align__(16) float g_v[MTOT * D_];
__device__ __align__(16) __half g_xh[MTOT * D_];
__device__ __align__(16) __half g_xl[MTOT * D_];
__device__ __align__(16) __half g_wh[3 * D_ * D_];

// ---------------------------------------------------------------------------
__device__ __forceinline__ uint32_t smem_u32(const void* p) {
    uint32_t a;
    asm("{ .reg .u64 t; cvta.to.shared.u64 t, %1; cvt.u32.u64 %0, t; }" : "=r"(a) : "l"(p));
    return a;
}

__device__ __forceinline__ void cpa16(uint32_t dst, const void* src) {
    asm volatile("cp.async.cg.shared.global [%0], [%1], 16;" :: "r"(dst), "l"(src));
}

__device__ __forceinline__ void ldsm_x4(uint32_t* r, uint32_t addr) {
    asm volatile("ldmatrix.sync.aligned.m8n8.x4.shared.b16 {%0,%1,%2,%3}, [%4];"
                 : "=r"(r[0]), "=r"(r[1]), "=r"(r[2]), "=r"(r[3]) : "r"(addr));
}

__device__ __forceinline__ void mma16816(float* d, const uint32_t* a, const uint32_t* b) {
    asm volatile(
        "mma.sync.aligned.m16n8k16.row.col.f32.f16.f16.f32 "
        "{%0,%1,%2,%3}, {%4,%5,%6,%7}, {%8,%9}, {%0,%1,%2,%3};"
        : "+f"(d[0]), "+f"(d[1]), "+f"(d[2]), "+f"(d[3])
        : "r"(a[0]), "r"(a[1]), "r"(a[2]), "r"(a[3]), "r"(b[0]), "r"(b[1]));
}

// Packed f32x2 ops (sm_100+ base ISA)
__device__ __forceinline__ u64t fma2(u64t a, u64t b, u64t c) {
    u64t d;
    asm("fma.rn.f32x2 %0, %1, %2, %3;" : "=l"(d) : "l"(a), "l"(b), "l"(c));
    return d;
}
__device__ __forceinline__ u64t add2(u64t a, u64t b) {
    u64t d;
    asm("add.rn.f32x2 %0, %1, %2;" : "=l"(d) : "l"(a), "l"(b));
    return d;
}
__device__ __forceinline__ u64t pack2(float lo, float hi) {
    u64t d;
    asm("mov.b64 %0, {%1, %2};" : "=l"(d) : "f"(lo), "f"(hi));
    return d;
}
__device__ __forceinline__ void unpack2(u64t v, float& a, float& b) {
    asm("mov.b64 {%0, %1}, %2;" : "=f"(a), "=f"(b) : "l"(v));
}
__device__ __forceinline__ float ex2f(float x) {
    float r;
    asm("ex2.approx.f32 %0, %1;" : "=f"(r) : "f"(x));
    return r;
}
__device__ __forceinline__ float rcpf(float x) {
    float r;
    asm("rcp.approx.f32 %0, %1;" : "=f"(r) : "f"(x));
    return r;
}

// ---------------------------------------------------------------------------
// Kernel 0a: X fp32 -> (fp16 hi, fp16 lo) split.  x = hi + lo, |lo| <= 2^-11|x|
// ---------------------------------------------------------------------------
__global__ __launch_bounds__(256)
void cvt_x(const float* __restrict__ src, __half* __restrict__ hi,
           __half* __restrict__ lo, int n4)
{
    int i = blockIdx.x * blockDim.x + threadIdx.x;
    if (i >= n4) return;
    float4 v = ((const float4*)src)[i];
    float a[4] = {v.x, v.y, v.z, v.w};
    __half h[4], l[4];
#pragma unroll
    for (int j = 0; j < 4; j++) {
        h[j] = __float2half(a[j]);
        l[j] = __float2half(a[j] - __half2float(h[j]));
    }
    ((uint2*)hi)[i] = *(uint2*)h;
    ((uint2*)lo)[i] = *(uint2*)l;
}

// Kernel 0b: weights -> fp16 hi only (truncation error ~2^-12 rel, budgeted)
__global__ __launch_bounds__(256)
void cvt_w(const float* __restrict__ Wq, const float* __restrict__ Wk,
           const float* __restrict__ Wv, __half* __restrict__ hi)
{
    const int z = blockIdx.z;
    const float* src = (z == 0) ? Wq : (z == 1) ? Wk : Wv;
    const int n4 = D_ * D_ / 4;
    int i = blockIdx.x * blockDim.x + threadIdx.x;
    if (i >= n4) return;
    float4 v = ((const float4*)src)[i];
    float a[4] = {v.x, v.y, v.z, v.w};
    __half h[4];
#pragma unroll
    for (int j = 0; j < 4; j++) h[j] = __float2half(a[j]);
    ((uint2*)(hi + (long)z * D_ * D_))[i] = *(uint2*)h;
}

// ---------------------------------------------------------------------------
// Kernel 1: fp16 2-term split GEMM via mma.sync (HMMA).
// O = (Xh + Xl) * Wh^T.  Block tile 128x128, BK=32, 256 threads
// (8 warps: 4M x 2N, warp tile 32x64). 2 CTAs/SM, double-buffered cp.async,
// padded stride 40 (conflict-free LDSM). B fragment shared by both terms.
// ---------------------------------------------------------------------------
#define GTM 128
#define GTN 128
#define GTK 32
#define NCHUNK (D_ / GTK)            // 32
#define LDT 40                        // padded stride in elements
#define TILE_BYTES (128 * LDT * 2)    // 10240 B
#define STAGE_BYTES (3 * TILE_BYTES)  // Ah Al Bh = 30720 B
#define GEMM_SMEM (2 * STAGE_BYTES)   // 61440 B

__device__ __forceinline__ void load_chunk(uint32_t buf,
    const __half* __restrict__ Ah, const __half* __restrict__ Al,
    const __half* __restrict__ Bh, int k0, int tid)
{
#pragma unroll
    for (int i = 0; i < 2; i++) {
        int idx = tid + (i << 8);
        int row = idx >> 2;
        int seg = idx & 3;
        uint32_t so = (uint32_t)(row * (LDT * 2) + seg * 16);
        long go = (long)row * D_ + k0 + seg * 8;
        cpa16(buf + so,                  Ah + go);
        cpa16(buf + TILE_BYTES + so,     Al + go);
        cpa16(buf + 2 * TILE_BYTES + so, Bh + go);
    }
}

__global__ __launch_bounds__(256, 2)
void qkv_tc()
{
    extern __shared__ char smem[];
    const uint32_t sb = smem_u32(smem);
    const int tid = threadIdx.x;
    const int wid = tid >> 5;
    const int lid = tid & 31;

    const int n0 = blockIdx.x * GTN;
    const int m0 = blockIdx.y * GTM;
    const int z  = blockIdx.z;

    const __half* Ah = g_xh + (long)m0 * D_;
    const __half* Al = g_xl + (long)m0 * D_;
    const __half* Bh = g_wh + (long)z * D_ * D_ + (long)n0 * D_;
    float* O = (z == 0) ? g_q : (z == 1) ? g_k : g_v;

    const int warp_m = (wid & 3) * 32;
    const int warp_n = (wid >> 2) * 64;

    const int a_row = ((lid >> 3) & 1) * 8 + (lid & 7);
    const int a_col = (lid >> 4) * 8;
    const int mi    = lid >> 3;
    const int b_row = (mi >> 1) * 8 + (lid & 7);
    const int b_col = (mi & 1) * 8;

    float acc[2][8][4];
#pragma unroll
    for (int mt = 0; mt < 2; mt++)
#pragma unroll
        for (int nt = 0; nt < 8; nt++)
#pragma unroll
            for (int r = 0; r < 4; r++) acc[mt][nt][r] = 0.f;

    load_chunk(sb, Ah, Al, Bh, 0, tid);
    asm volatile("cp.async.commit_group;" ::: "memory");

#pragma unroll 1
    for (int c = 0; c < NCHUNK; c++) {
        asm volatile("cp.async.wait_group 0;" ::: "memory");
        __syncthreads();

        if (c + 1 < NCHUNK) {
            load_chunk(sb + ((c + 1) & 1) * STAGE_BYTES, Ah, Al, Bh,
                       (c + 1) * GTK, tid);
            asm volatile("cp.async.commit_group;" ::: "memory");
        }

        const uint32_t st = sb + (c & 1) * STAGE_BYTES;
        const uint32_t tAh = st;
        const uint32_t tAl = st + TILE_BYTES;
        const uint32_t tBh = st + 2 * TILE_BYTES;

#pragma unroll
        for (int ks = 0; ks < 2; ks++) {
            const int kc = ks * 16;
            uint32_t ah[2][4], al[2][4];
#pragma unroll
            for (int mt = 0; mt < 2; mt++) {
                const uint32_t off =
                    (uint32_t)((warp_m + mt * 16 + a_row) * LDT + kc + a_col) * 2;
                ldsm_x4(ah[mt], tAh + off);
                ldsm_x4(al[mt], tAl + off);
            }
#pragma unroll
            for (int p = 0; p < 4; p++) {
                const uint32_t off =
                    (uint32_t)((warp_n + p * 16 + b_row) * LDT + kc + b_col) * 2;
                uint32_t bh[4];
                ldsm_x4(bh, tBh + off);
                // term-major: same-acc dependency distance = 4 MMAs
#pragma unroll
                for (int half = 0; half < 2; half++)
#pragma unroll
                    for (int mt = 0; mt < 2; mt++)
                        mma16816(acc[mt][p * 2 + half], ah[mt], &bh[half * 2]);
#pragma unroll
                for (int half = 0; half < 2; half++)
#pragma unroll
                    for (int mt = 0; mt < 2; mt++)
                        mma16816(acc[mt][p * 2 + half], al[mt], &bh[half * 2]);
            }
        }
        __syncthreads();
    }

    const int er = lid >> 2;
    const int ec = (lid & 3) * 2;
#pragma unroll
    for (int mt = 0; mt < 2; mt++)
#pragma unroll
        for (int nt = 0; nt < 8; nt++) {
            float* p0 = O + (long)(m0 + warp_m + mt * 16 + er) * D_
                          + n0 + warp_n + nt * 8 + ec;
            float* p1 = p0 + 8 * D_;
            *(float2*)p0 = make_float2(acc[mt][nt][0], acc[mt][nt][1]);
            *(float2*)p1 = make_float2(acc[mt][nt][2], acc[mt][nt][3]);
        }
}

// ---------------------------------------------------------------------------
// Kernel 2: attention per (chunk c, batch b). Single-pass softmax in log2
// domain. Packed f32x2 FMA. (Unchanged from R5 — known-good at 267us.)
// ---------------------------------------------------------------------------
__global__ __launch_bounds__(256)
void attn(const float* __restrict__ mask, float* __restrict__ out)
{
    __shared__ float k_s[S_][H_];
    __shared__ float v_s[S_][H_];
    __shared__ float m_s[S_];

    const int c = blockIdx.x;
    const int b = blockIdx.y;
    const int t = threadIdx.x;

    const long base = (long)(b * S_) * D_ + c * H_;

    {
        const int r0 = t >> 2;
        const int c4 = (t & 3) << 2;
#pragma unroll
        for (int p = 0; p < 4; p++) {
            const int row = p * 64 + r0;
            *(float4*)&k_s[row][c4] = *(const float4*)&g_k[base + (long)row * D_ + c4];
            *(float4*)&v_s[row][c4] = *(const float4*)&g_v[base + (long)row * D_ + c4];
        }
    }
    const float mq_raw = mask[b * S_ + t];
    m_s[t] = (mq_raw > 0.f) ? 1.0f : 0.0f;

    u64t q2[8];
#pragma unroll
    for (int i = 0; i < 4; i++) {
        ulonglong2 qq = *(const ulonglong2*)&g_q[base + (long)t * D_ + i * 4];
        q2[i * 2 + 0] = qq.x;
        q2[i * 2 + 1] = qq.y;
    }
    __syncthreads();

    const float scale2 = (mq_raw > 0.f) ? (1.4426950408889634f * 0.03125f) : 0.0f;

    float s = 0.f;
    u64t o2[8];
#pragma unroll
    for (int h = 0; h < 8; h++) o2[h] = 0ull;

#pragma unroll 4
    for (int kk = 0; kk < S_; kk++) {
        const ulonglong2 ka = *(const ulonglong2*)&k_s[kk][0];
        const ulonglong2 kb = *(const ulonglong2*)&k_s[kk][4];
        const ulonglong2 kc = *(const ulonglong2*)&k_s[kk][8];
        const ulonglong2 kd = *(const ulonglong2*)&k_s[kk][12];

        u64t da = fma2(q2[0], ka.x, 0ull);
        u64t db = fma2(q2[1], ka.y, 0ull);
        da = fma2(q2[2], kb.x, da);
        db = fma2(q2[3], kb.y, db);
        da = fma2(q2[4], kc.x, da);
        db = fma2(q2[5], kc.y, db);
        da = fma2(q2[6], kd.x, da);
        db = fma2(q2[7], kd.y, db);
        const u64t dd = add2(da, db);
        float f0, f1;
        unpack2(dd, f0, f1);
        const float d = f0 + f1;

        const float l2 = fmaf(m_s[kk], fmaf(d, scale2, 100.f), -100.f);
        const float w = ex2f(l2);
        s += w;

        const u64t w2 = pack2(w, w);
        const ulonglong2 va = *(const ulonglong2*)&v_s[kk][0];
        const ulonglong2 vb = *(const ulonglong2*)&v_s[kk][4];
        const ulonglong2 vc = *(const ulonglong2*)&v_s[kk][8];
        const ulonglong2 vd = *(const ulonglong2*)&v_s[kk][12];
        o2[0] = fma2(w2, va.x, o2[0]);
        o2[1] = fma2(w2, va.y, o2[1]);
        o2[2] = fma2(w2, vb.x, o2[2]);
        o2[3] = fma2(w2, vb.y, o2[3]);
        o2[4] = fma2(w2, vc.x, o2[4]);
        o2[5] = fma2(w2, vc.y, o2[5]);
        o2[6] = fma2(w2, vd.x, o2[6]);
        o2[7] = fma2(w2, vd.y, o2[7]);
    }

    const float inv = rcpf(s);
    float* op = out + base + (long)t * D_;
#pragma unroll
    for (int i = 0; i < 4; i++) {
        float a0, a1, a2, a3;
        unpack2(o2[i * 2 + 0], a0, a1);
        unpack2(o2[i * 2 + 1], a2, a3);
        float4 v = make_float4(a0 * inv, a1 * inv, a2 * inv, a3 * inv);
        *(float4*)(op + i * 4) = v;
    }
}

// ---------------------------------------------------------------------------
extern "C" void kernel_launch(void* const* d_in, const int* in_sizes, int n_in,
                              void* d_out, int out_size)
{
    const float* x    = (const float*)d_in[0];
    const float* mask = (const float*)d_in[1];
    const float* Wq   = (const float*)d_in[2];
    const float* Wk   = (const float*)d_in[3];
    const float* Wv   = (const float*)d_in[4];
    float* out = (float*)d_out;

    __half *xh, *xl, *wh;
    cudaGetSymbolAddress((void**)&xh, g_xh);
    cudaGetSymbolAddress((void**)&xl, g_xl);
    cudaGetSymbolAddress((void**)&wh, g_wh);

    cvt_x<<<(MTOT * D_ / 4 + 255) / 256, 256>>>(x, xh, xl, MTOT * D_ / 4);
    dim3 gw((D_ * D_ / 4 + 255) / 256, 1, 3);
    cvt_w<<<gw, 256>>>(Wq, Wk, Wv, wh);

    static bool attr_set = false;
    if (!attr_set) {
        cudaFuncSetAttribute(qkv_tc, cudaFuncAttributeMaxDynamicSharedMemorySize, GEMM_SMEM);
        attr_set = true;
    }

    dim3 g1(D_ / GTN, MTOT / GTM, 3);
    qkv_tc<<<g1, 256, GEMM_SMEM>>>();

    dim3 g2(C_, B_);
    attn<<<g2, 256>>>(mask, out);
}

// round 8
// speedup vs baseline: 4.1894x; 1.3484x over previous
#include <cuda_runtime.h>
#include <cuda_fp16.h>
#include <cstdint>

// Problem constants
#define B_    32
#define S_    256
#define D_    1024
#define H_    16
#define C_    64
#define MTOT  (B_ * S_)   // 8192

typedef unsigned long long u64t;

// Scratch (allocation-free rule: device globals)
__device__ __align__(16) float g_q[MTOT * D_];
__device__ __align__(16) float g_k[MTOT * D_];
__device__ __align__(16) float g_v[MTOT * D_];
__device__ __align__(16) __half g_xh[MTOT * D_];
__device__ __align__(16) __half g_wh[3 * D_ * D_];

// ---------------------------------------------------------------------------
__device__ __forceinline__ uint32_t smem_u32(const void* p) {
    uint32_t a;
    asm("{ .reg .u64 t; cvta.to.shared.u64 t, %1; cvt.u32.u64 %0, t; }" : "=r"(a) : "l"(p));
    return a;
}

__device__ __forceinline__ void cpa16(uint32_t dst, const void* src) {
    asm volatile("cp.async.cg.shared.global [%0], [%1], 16;" :: "r"(dst), "l"(src));
}

__device__ __forceinline__ void ldsm_x4(uint32_t* r, uint32_t addr) {
    asm volatile("ldmatrix.sync.aligned.m8n8.x4.shared.b16 {%0,%1,%2,%3}, [%4];"
                 : "=r"(r[0]), "=r"(r[1]), "=r"(r[2]), "=r"(r[3]) : "r"(addr));
}

__device__ __forceinline__ void mma16816(float* d, const uint32_t* a, const uint32_t* b) {
    asm volatile(
        "mma.sync.aligned.m16n8k16.row.col.f32.f16.f16.f32 "
        "{%0,%1,%2,%3}, {%4,%5,%6,%7}, {%8,%9}, {%0,%1,%2,%3};"
        : "+f"(d[0]), "+f"(d[1]), "+f"(d[2]), "+f"(d[3])
        : "r"(a[0]), "r"(a[1]), "r"(a[2]), "r"(a[3]), "r"(b[0]), "r"(b[1]));
}

// Packed f32x2 ops (sm_100+ base ISA)
__device__ __forceinline__ u64t fma2(u64t a, u64t b, u64t c) {
    u64t d;
    asm("fma.rn.f32x2 %0, %1, %2, %3;" : "=l"(d) : "l"(a), "l"(b), "l"(c));
    return d;
}
__device__ __forceinline__ u64t add2(u64t a, u64t b) {
    u64t d;
    asm("add.rn.f32x2 %0, %1, %2;" : "=l"(d) : "l"(a), "l"(b));
    return d;
}
__device__ __forceinline__ u64t pack2(float lo, float hi) {
    u64t d;
    asm("mov.b64 %0, {%1, %2};" : "=l"(d) : "f"(lo), "f"(hi));
    return d;
}
__device__ __forceinline__ void unpack2(u64t v, float& a, float& b) {
    asm("mov.b64 {%0, %1}, %2;" : "=f"(a), "=f"(b) : "l"(v));
}
__device__ __forceinline__ float ex2f(float x) {
    float r;
    asm("ex2.approx.f32 %0, %1;" : "=f"(r) : "f"(x));
    return r;
}
__device__ __forceinline__ float rcpf(float x) {
    float r;
    asm("rcp.approx.f32 %0, %1;" : "=f"(r) : "f"(x));
    return r;
}

// ---------------------------------------------------------------------------
// Kernel 0a: X fp32 -> fp16 (truncation within error budget)
// ---------------------------------------------------------------------------
__global__ __launch_bounds__(256)
void cvt_x(const float* __restrict__ src, __half* __restrict__ hi, int n4)
{
    int i = blockIdx.x * blockDim.x + threadIdx.x;
    if (i >= n4) return;
    float4 v = ((const float4*)src)[i];
    float a[4] = {v.x, v.y, v.z, v.w};
    __half h[4];
#pragma unroll
    for (int j = 0; j < 4; j++) h[j] = __float2half(a[j]);
    ((uint2*)hi)[i] = *(uint2*)h;
}

// Kernel 0b: weights -> fp16
__global__ __launch_bounds__(256)
void cvt_w(const float* __restrict__ Wq, const float* __restrict__ Wk,
           const float* __restrict__ Wv, __half* __restrict__ hi)
{
    const int z = blockIdx.z;
    const float* src = (z == 0) ? Wq : (z == 1) ? Wk : Wv;
    const int n4 = D_ * D_ / 4;
    int i = blockIdx.x * blockDim.x + threadIdx.x;
    if (i >= n4) return;
    float4 v = ((const float4*)src)[i];
    float a[4] = {v.x, v.y, v.z, v.w};
    __half h[4];
#pragma unroll
    for (int j = 0; j < 4; j++) h[j] = __float2half(a[j]);
    ((uint2*)(hi + (long)z * D_ * D_))[i] = *(uint2*)h;
}

// ---------------------------------------------------------------------------
// Kernel 1: fp16 single-term GEMM via mma.sync (HMMA).
// O = Xh * Wh^T.  Block tile 128x128, BK=32, 256 threads
// (8 warps: 4M x 2N, warp tile 32x64). 2 CTAs/SM, double-buffered cp.async,
// padded stride 40 (conflict-free LDSM).
// ---------------------------------------------------------------------------
#define GTM 128
#define GTN 128
#define GTK 32
#define NCHUNK (D_ / GTK)            // 32
#define LDT 40                        // padded stride in elements
#define TILE_BYTES (128 * LDT * 2)    // 10240 B
#define STAGE_BYTES (2 * TILE_BYTES)  // Ah Bh = 20480 B
#define GEMM_SMEM (2 * STAGE_BYTES)   // 40960 B

__device__ __forceinline__ void load_chunk(uint32_t buf,
    const __half* __restrict__ Ah, const __half* __restrict__ Bh,
    int k0, int tid)
{
#pragma unroll
    for (int i = 0; i < 2; i++) {
        int idx = tid + (i << 8);
        int row = idx >> 2;
        int seg = idx & 3;
        uint32_t so = (uint32_t)(row * (LDT * 2) + seg * 16);
        long go = (long)row * D_ + k0 + seg * 8;
        cpa16(buf + so,              Ah + go);
        cpa16(buf + TILE_BYTES + so, Bh + go);
    }
}

__global__ __launch_bounds__(256, 2)
void qkv_tc()
{
    extern __shared__ char smem[];
    const uint32_t sb = smem_u32(smem);
    const int tid = threadIdx.x;
    const int wid = tid >> 5;
    const int lid = tid & 31;

    const int n0 = blockIdx.x * GTN;
    const int m0 = blockIdx.y * GTM;
    const int z  = blockIdx.z;

    const __half* Ah = g_xh + (long)m0 * D_;
    const __half* Bh = g_wh + (long)z * D_ * D_ + (long)n0 * D_;
    float* O = (z == 0) ? g_q : (z == 1) ? g_k : g_v;

    const int warp_m = (wid & 3) * 32;
    const int warp_n = (wid >> 2) * 64;

    const int a_row = ((lid >> 3) & 1) * 8 + (lid & 7);
    const int a_col = (lid >> 4) * 8;
    const int mi    = lid >> 3;
    const int b_row = (mi >> 1) * 8 + (lid & 7);
    const int b_col = (mi & 1) * 8;

    float acc[2][8][4];
#pragma unroll
    for (int mt = 0; mt < 2; mt++)
#pragma unroll
        for (int nt = 0; nt < 8; nt++)
#pragma unroll
            for (int r = 0; r < 4; r++) acc[mt][nt][r] = 0.f;

    load_chunk(sb, Ah, Bh, 0, tid);
    asm volatile("cp.async.commit_group;" ::: "memory");

#pragma unroll 1
    for (int c = 0; c < NCHUNK; c++) {
        asm volatile("cp.async.wait_group 0;" ::: "memory");
        __syncthreads();

        if (c + 1 < NCHUNK) {
            load_chunk(sb + ((c + 1) & 1) * STAGE_BYTES, Ah, Bh,
                       (c + 1) * GTK, tid);
            asm volatile("cp.async.commit_group;" ::: "memory");
        }

        const uint32_t st = sb + (c & 1) * STAGE_BYTES;
        const uint32_t tAh = st;
        const uint32_t tBh = st + TILE_BYTES;

#pragma unroll
        for (int ks = 0; ks < 2; ks++) {
            const int kc = ks * 16;
            uint32_t ah[2][4];
#pragma unroll
            for (int mt = 0; mt < 2; mt++) {
                const uint32_t off =
                    (uint32_t)((warp_m + mt * 16 + a_row) * LDT + kc + a_col) * 2;
                ldsm_x4(ah[mt], tAh + off);
            }
#pragma unroll
            for (int p = 0; p < 4; p++) {
                const uint32_t off =
                    (uint32_t)((warp_n + p * 16 + b_row) * LDT + kc + b_col) * 2;
                uint32_t bh[4];
                ldsm_x4(bh, tBh + off);
#pragma unroll
                for (int half = 0; half < 2; half++)
#pragma unroll
                    for (int mt = 0; mt < 2; mt++)
                        mma16816(acc[mt][p * 2 + half], ah[mt], &bh[half * 2]);
            }
        }
        __syncthreads();
    }

    const int er = lid >> 2;
    const int ec = (lid & 3) * 2;
#pragma unroll
    for (int mt = 0; mt < 2; mt++)
#pragma unroll
        for (int nt = 0; nt < 8; nt++) {
            float* p0 = O + (long)(m0 + warp_m + mt * 16 + er) * D_
                          + n0 + warp_n + nt * 8 + ec;
            float* p1 = p0 + 8 * D_;
            *(float2*)p0 = make_float2(acc[mt][nt][0], acc[mt][nt][1]);
            *(float2*)p1 = make_float2(acc[mt][nt][2], acc[mt][nt][3]);
        }
}

// ---------------------------------------------------------------------------
// Kernel 2: attention per (chunk c, batch b). 128 threads, 2 queries/thread
// (rows t and t+128) so each broadcast k/v smem load serves two queries —
// halves L1 wavefronts (was the 90%-L1 bottleneck). Single-pass log2 softmax,
// packed f32x2 FMA.
// ---------------------------------------------------------------------------
__global__ __launch_bounds__(128)
void attn(const float* __restrict__ mask, float* __restrict__ out)
{
    __shared__ float k_s[S_][H_];
    __shared__ float v_s[S_][H_];
    __shared__ float m_s[S_];

    const int c = blockIdx.x;
    const int b = blockIdx.y;
    const int t = threadIdx.x;          // 0..127

    const long base = (long)(b * S_) * D_ + c * H_;

    // Stage K, V (128 threads x float4: 32 rows per pass, 8 passes)
    {
        const int r0 = t >> 2;          // 0..31
        const int c4 = (t & 3) << 2;
#pragma unroll
        for (int p = 0; p < 8; p++) {
            const int row = p * 32 + r0;
            *(float4*)&k_s[row][c4] = *(const float4*)&g_k[base + (long)row * D_ + c4];
            *(float4*)&v_s[row][c4] = *(const float4*)&g_v[base + (long)row * D_ + c4];
        }
    }
    const float mqa_raw = mask[b * S_ + t];
    const float mqb_raw = mask[b * S_ + t + 128];
    m_s[t]       = (mqa_raw > 0.f) ? 1.0f : 0.0f;
    m_s[t + 128] = (mqb_raw > 0.f) ? 1.0f : 0.0f;

    // two query rows, packed as 8 f32x2 each
    u64t qa[8], qb[8];
#pragma unroll
    for (int i = 0; i < 4; i++) {
        ulonglong2 va = *(const ulonglong2*)&g_q[base + (long)t * D_ + i * 4];
        qa[i * 2 + 0] = va.x; qa[i * 2 + 1] = va.y;
        ulonglong2 vb = *(const ulonglong2*)&g_q[base + (long)(t + 128) * D_ + i * 4];
        qb[i * 2 + 0] = vb.x; qb[i * 2 + 1] = vb.y;
    }
    __syncthreads();

    const float sA = (mqa_raw > 0.f) ? (1.4426950408889634f * 0.03125f) : 0.0f;
    const float sB = (mqb_raw > 0.f) ? (1.4426950408889634f * 0.03125f) : 0.0f;

    float ssa = 0.f, ssb = 0.f;
    u64t oa[8], ob[8];
#pragma unroll
    for (int h = 0; h < 8; h++) { oa[h] = 0ull; ob[h] = 0ull; }

#pragma unroll 2
    for (int kk = 0; kk < S_; kk++) {
        const ulonglong2 k0 = *(const ulonglong2*)&k_s[kk][0];
        const ulonglong2 k1 = *(const ulonglong2*)&k_s[kk][4];
        const ulonglong2 k2 = *(const ulonglong2*)&k_s[kk][8];
        const ulonglong2 k3 = *(const ulonglong2*)&k_s[kk][12];

        // query A dot
        u64t da = fma2(qa[0], k0.x, 0ull);
        u64t db = fma2(qa[1], k0.y, 0ull);
        da = fma2(qa[2], k1.x, da);
        db = fma2(qa[3], k1.y, db);
        da = fma2(qa[4], k2.x, da);
        db = fma2(qa[5], k2.y, db);
        da = fma2(qa[6], k3.x, da);
        db = fma2(qa[7], k3.y, db);
        // query B dot (independent chain)
        u64t ea = fma2(qb[0], k0.x, 0ull);
        u64t eb = fma2(qb[1], k0.y, 0ull);
        ea = fma2(qb[2], k1.x, ea);
        eb = fma2(qb[3], k1.y, eb);
        ea = fma2(qb[4], k2.x, ea);
        eb = fma2(qb[5], k2.y, eb);
        ea = fma2(qb[6], k3.x, ea);
        eb = fma2(qb[7], k3.y, eb);

        float a0, a1, b0, b1;
        unpack2(add2(da, db), a0, a1);
        unpack2(add2(ea, eb), b0, b1);
        const float dA = a0 + a1;
        const float dB = b0 + b1;

        const float mk = m_s[kk];
        const float lA = fmaf(mk, fmaf(dA, sA, 100.f), -100.f);
        const float lB = fmaf(mk, fmaf(dB, sB, 100.f), -100.f);
        const float wA = ex2f(lA);
        const float wB = ex2f(lB);
        ssa += wA;
        ssb += wB;

        const u64t wA2 = pack2(wA, wA);
        const u64t wB2 = pack2(wB, wB);
        const ulonglong2 v0 = *(const ulonglong2*)&v_s[kk][0];
        const ulonglong2 v1 = *(const ulonglong2*)&v_s[kk][4];
        const ulonglong2 v2 = *(const ulonglong2*)&v_s[kk][8];
        const ulonglong2 v3 = *(const ulonglong2*)&v_s[kk][12];
        oa[0] = fma2(wA2, v0.x, oa[0]);
        ob[0] = fma2(wB2, v0.x, ob[0]);
        oa[1] = fma2(wA2, v0.y, oa[1]);
        ob[1] = fma2(wB2, v0.y, ob[1]);
        oa[2] = fma2(wA2, v1.x, oa[2]);
        ob[2] = fma2(wB2, v1.x, ob[2]);
        oa[3] = fma2(wA2, v1.y, oa[3]);
        ob[3] = fma2(wB2, v1.y, ob[3]);
        oa[4] = fma2(wA2, v2.x, oa[4]);
        ob[4] = fma2(wB2, v2.x, ob[4]);
        oa[5] = fma2(wA2, v2.y, oa[5]);
        ob[5] = fma2(wB2, v2.y, ob[5]);
        oa[6] = fma2(wA2, v3.x, oa[6]);
        ob[6] = fma2(wB2, v3.x, ob[6]);
        oa[7] = fma2(wA2, v3.y, oa[7]);
        ob[7] = fma2(wB2, v3.y, ob[7]);
    }

    const float invA = rcpf(ssa);
    const float invB = rcpf(ssb);
    float* opA = out + base + (long)t * D_;
    float* opB = out + base + (long)(t + 128) * D_;
#pragma unroll
    for (int i = 0; i < 4; i++) {
        float a0, a1, a2, a3;
        unpack2(oa[i * 2 + 0], a0, a1);
        unpack2(oa[i * 2 + 1], a2, a3);
        *(float4*)(opA + i * 4) = make_float4(a0 * invA, a1 * invA, a2 * invA, a3 * invA);
        float b0, b1, b2, b3;
        unpack2(ob[i * 2 + 0], b0, b1);
        unpack2(ob[i * 2 + 1], b2, b3);
        *(float4*)(opB + i * 4) = make_float4(b0 * invB, b1 * invB, b2 * invB, b3 * invB);
    }
}

// ---------------------------------------------------------------------------
extern "C" void kernel_launch(void* const* d_in, const int* in_sizes, int n_in,
                              void* d_out, int out_size)
{
    const float* x    = (const float*)d_in[0];
    const float* mask = (const float*)d_in[1];
    const float* Wq   = (const float*)d_in[2];
    const float* Wk   = (const float*)d_in[3];
    const float* Wv   = (const float*)d_in[4];
    float* out = (float*)d_out;

    __half *xh, *wh;
    cudaGetSymbolAddress((void**)&xh, g_xh);
    cudaGetSymbolAddress((void**)&wh, g_wh);

    cvt_x<<<(MTOT * D_ / 4 + 255) / 256, 256>>>(x, xh, MTOT * D_ / 4);
    dim3 gw((D_ * D_ / 4 + 255) / 256, 1, 3);
    cvt_w<<<gw, 256>>>(Wq, Wk, Wv, wh);

    static bool attr_set = false;
    if (!attr_set) {
        cudaFuncSetAttribute(qkv_tc, cudaFuncAttributeMaxDynamicSharedMemorySize, GEMM_SMEM);
        attr_set = true;
    }

    dim3 g1(D_ / GTN, MTOT / GTM, 3);
    qkv_tc<<<g1, 256, GEMM_SMEM>>>();

    dim3 g2(C_, B_);
    attn<<<g2, 128>>>(mask, out);
}

// round 9
// speedup vs baseline: 7.4348x; 1.7747x over previous
#include <cuda_runtime.h>
#include <cuda_fp16.h>
#include <cstdint>

// Problem constants
#define B_    32
#define S_    256
#define D_    1024
#define H_    16
#define C_    64
#define MTOT  (B_ * S_)   // 8192

// Scratch (allocation-free rule: device globals)
__device__ __align__(16) __half g_qh[MTOT * D_];
__device__ __align__(16) __half g_kh[MTOT * D_];
__device__ __align__(16) __half g_vh[MTOT * D_];
__device__ __align__(16) __half g_xh[MTOT * D_];
__device__ __align__(16) __half g_wh[3 * D_ * D_];

// ---------------------------------------------------------------------------
__device__ __forceinline__ uint32_t smem_u32(const void* p) {
    uint32_t a;
    asm("{ .reg .u64 t; cvta.to.shared.u64 t, %1; cvt.u32.u64 %0, t; }" : "=r"(a) : "l"(p));
    return a;
}

__device__ __forceinline__ void cpa16(uint32_t dst, const void* src) {
    asm volatile("cp.async.cg.shared.global [%0], [%1], 16;" :: "r"(dst), "l"(src));
}

__device__ __forceinline__ void ldsm_x4(uint32_t* r, uint32_t addr) {
    asm volatile("ldmatrix.sync.aligned.m8n8.x4.shared.b16 {%0,%1,%2,%3}, [%4];"
                 : "=r"(r[0]), "=r"(r[1]), "=r"(r[2]), "=r"(r[3]) : "r"(addr));
}
__device__ __forceinline__ void ldsm_x4_t(uint32_t* r, uint32_t addr) {
    asm volatile("ldmatrix.sync.aligned.m8n8.x4.trans.shared.b16 {%0,%1,%2,%3}, [%4];"
                 : "=r"(r[0]), "=r"(r[1]), "=r"(r[2]), "=r"(r[3]) : "r"(addr));
}

__device__ __forceinline__ void mma16816(float* d, const uint32_t* a, const uint32_t* b) {
    asm volatile(
        "mma.sync.aligned.m16n8k16.row.col.f32.f16.f16.f32 "
        "{%0,%1,%2,%3}, {%4,%5,%6,%7}, {%8,%9}, {%0,%1,%2,%3};"
        : "+f"(d[0]), "+f"(d[1]), "+f"(d[2]), "+f"(d[3])
        : "r"(a[0]), "r"(a[1]), "r"(a[2]), "r"(a[3]), "r"(b[0]), "r"(b[1]));
}

__device__ __forceinline__ float ex2f(float x) {
    float r;
    asm("ex2.approx.f32 %0, %1;" : "=f"(r) : "f"(x));
    return r;
}
__device__ __forceinline__ float rcpf(float x) {
    float r;
    asm("rcp.approx.f32 %0, %1;" : "=f"(r) : "f"(x));
    return r;
}

// ---------------------------------------------------------------------------
// Kernel 0: fp32 -> fp16 conversions
// ---------------------------------------------------------------------------
__global__ __launch_bounds__(256)
void cvt_x(const float* __restrict__ src, __half* __restrict__ hi, int n4)
{
    int i = blockIdx.x * blockDim.x + threadIdx.x;
    if (i >= n4) return;
    float4 v = ((const float4*)src)[i];
    float a[4] = {v.x, v.y, v.z, v.w};
    __half h[4];
#pragma unroll
    for (int j = 0; j < 4; j++) h[j] = __float2half(a[j]);
    ((uint2*)hi)[i] = *(uint2*)h;
}

__global__ __launch_bounds__(256)
void cvt_w(const float* __restrict__ Wq, const float* __restrict__ Wk,
           const float* __restrict__ Wv, __half* __restrict__ hi)
{
    const int z = blockIdx.z;
    const float* src = (z == 0) ? Wq : (z == 1) ? Wk : Wv;
    const int n4 = D_ * D_ / 4;
    int i = blockIdx.x * blockDim.x + threadIdx.x;
    if (i >= n4) return;
    float4 v = ((const float4*)src)[i];
    float a[4] = {v.x, v.y, v.z, v.w};
    __half h[4];
#pragma unroll
    for (int j = 0; j < 4; j++) h[j] = __float2half(a[j]);
    ((uint2*)(hi + (long)z * D_ * D_))[i] = *(uint2*)h;
}

// ---------------------------------------------------------------------------
// Kernel 1: fp16 GEMM via mma.sync -> fp16 Q/K/V outputs.
// Block tile 128x128, BK=32, 256 threads (8 warps: 4M x 2N). 2 CTAs/SM.
// ---------------------------------------------------------------------------
#define GTM 128
#define GTN 128
#define GTK 32
#define NCHUNK (D_ / GTK)            // 32
#define LDT 40
#define TILE_BYTES (128 * LDT * 2)    // 10240 B
#define STAGE_BYTES (2 * TILE_BYTES)  // 20480 B
#define GEMM_SMEM (2 * STAGE_BYTES)   // 40960 B

__device__ __forceinline__ void load_chunk(uint32_t buf,
    const __half* __restrict__ Ah, const __half* __restrict__ Bh,
    int k0, int tid)
{
#pragma unroll
    for (int i = 0; i < 2; i++) {
        int idx = tid + (i << 8);
        int row = idx >> 2;
        int seg = idx & 3;
        uint32_t so = (uint32_t)(row * (LDT * 2) + seg * 16);
        long go = (long)row * D_ + k0 + seg * 8;
        cpa16(buf + so,              Ah + go);
        cpa16(buf + TILE_BYTES + so, Bh + go);
    }
}

__global__ __launch_bounds__(256, 2)
void qkv_tc()
{
    extern __shared__ char smem[];
    const uint32_t sb = smem_u32(smem);
    const int tid = threadIdx.x;
    const int wid = tid >> 5;
    const int lid = tid & 31;

    const int n0 = blockIdx.x * GTN;
    const int m0 = blockIdx.y * GTM;
    const int z  = blockIdx.z;

    const __half* Ah = g_xh + (long)m0 * D_;
    const __half* Bh = g_wh + (long)z * D_ * D_ + (long)n0 * D_;
    __half* O = (z == 0) ? g_qh : (z == 1) ? g_kh : g_vh;

    const int warp_m = (wid & 3) * 32;
    const int warp_n = (wid >> 2) * 64;

    const int a_row = ((lid >> 3) & 1) * 8 + (lid & 7);
    const int a_col = (lid >> 4) * 8;
    const int mi    = lid >> 3;
    const int b_row = (mi >> 1) * 8 + (lid & 7);
    const int b_col = (mi & 1) * 8;

    float acc[2][8][4];
#pragma unroll
    for (int mt = 0; mt < 2; mt++)
#pragma unroll
        for (int nt = 0; nt < 8; nt++)
#pragma unroll
            for (int r = 0; r < 4; r++) acc[mt][nt][r] = 0.f;

    load_chunk(sb, Ah, Bh, 0, tid);
    asm volatile("cp.async.commit_group;" ::: "memory");

#pragma unroll 1
    for (int c = 0; c < NCHUNK; c++) {
        asm volatile("cp.async.wait_group 0;" ::: "memory");
        __syncthreads();

        if (c + 1 < NCHUNK) {
            load_chunk(sb + ((c + 1) & 1) * STAGE_BYTES, Ah, Bh,
                       (c + 1) * GTK, tid);
            asm volatile("cp.async.commit_group;" ::: "memory");
        }

        const uint32_t st = sb + (c & 1) * STAGE_BYTES;
        const uint32_t tAh = st;
        const uint32_t tBh = st + TILE_BYTES;

#pragma unroll
        for (int ks = 0; ks < 2; ks++) {
            const int kc = ks * 16;
            uint32_t ah[2][4];
#pragma unroll
            for (int mt = 0; mt < 2; mt++) {
                const uint32_t off =
                    (uint32_t)((warp_m + mt * 16 + a_row) * LDT + kc + a_col) * 2;
                ldsm_x4(ah[mt], tAh + off);
            }
#pragma unroll
            for (int p = 0; p < 4; p++) {
                const uint32_t off =
                    (uint32_t)((warp_n + p * 16 + b_row) * LDT + kc + b_col) * 2;
                uint32_t bh[4];
                ldsm_x4(bh, tBh + off);
#pragma unroll
                for (int half = 0; half < 2; half++)
#pragma unroll
                    for (int mt = 0; mt < 2; mt++)
                        mma16816(acc[mt][p * 2 + half], ah[mt], &bh[half * 2]);
            }
        }
        __syncthreads();
    }

    // Epilogue: fp16 stores
    const int er = lid >> 2;
    const int ec = (lid & 3) * 2;
#pragma unroll
    for (int mt = 0; mt < 2; mt++)
#pragma unroll
        for (int nt = 0; nt < 8; nt++) {
            const int row = m0 + warp_m + mt * 16 + er;
            const int col = n0 + warp_n + nt * 8 + ec;
            __half2 h01 = __floats2half2_rn(acc[mt][nt][0], acc[mt][nt][1]);
            __half2 h23 = __floats2half2_rn(acc[mt][nt][2], acc[mt][nt][3]);
            *(__half2*)(O + (long)row * D_ + col) = h01;
            *(__half2*)(O + (long)(row + 8) * D_ + col) = h23;
        }
}

// ---------------------------------------------------------------------------
// Kernel 2: tensor-core attention per (chunk c, batch b).
// 8 warps x 32 query rows. QK^T and P.V via mma.m16n8k16, single-pass log2
// softmax on fragments (row-scale + col-bias encode masking; masked-row ->
// uniform over unmasked keys, matching prior passing semantics).
// ---------------------------------------------------------------------------
#define ASTRIDE 24   // halves; 48B padded row
__global__ __launch_bounds__(256)
void attn(const float* __restrict__ mask, float* __restrict__ out)
{
    __shared__ __half q_s[S_][ASTRIDE];
    __shared__ __half k_s[S_][ASTRIDE];
    __shared__ __half v_s[S_][ASTRIDE];
    __shared__ float bias_s[S_];   // 0 or -100 per key
    __shared__ float qsc_s[S_];    // log2e/32 or 0 per query row

    const int c = blockIdx.x;
    const int b = blockIdx.y;
    const int t = threadIdx.x;
    const int wid = t >> 5;
    const int lane = t & 31;

    // Stage Q/K/V rows (fp16, 32B per row) and mask-derived vectors
    {
        const long gbase = (long)(b * S_ + t) * D_ + c * H_;
        const uint4* gq = (const uint4*)(g_qh + gbase);
        const uint4* gk = (const uint4*)(g_kh + gbase);
        const uint4* gv = (const uint4*)(g_vh + gbase);
        *(uint4*)&q_s[t][0] = gq[0];
        *(uint4*)&q_s[t][8] = gq[1];
        *(uint4*)&k_s[t][0] = gk[0];
        *(uint4*)&k_s[t][8] = gk[1];
        *(uint4*)&v_s[t][0] = gv[0];
        *(uint4*)&v_s[t][8] = gv[1];
        const float mv = mask[b * S_ + t];
        bias_s[t] = (mv > 0.f) ? 0.f : -100.f;
        qsc_s[t]  = (mv > 0.f) ? 0.045084234f : 0.f;   // log2(e)/32
    }
    __syncthreads();

    const uint32_t sq = smem_u32(q_s);
    const uint32_t sk = smem_u32(k_s);
    const uint32_t sv = smem_u32(v_s);

    const int m0 = wid * 32;

    // Q A-fragments (hoisted; constant across key chunks)
    const int a_row = lane & 15;
    const int a_coloff = (lane >> 4) * 16;  // bytes
    uint32_t aq[2][4];
#pragma unroll
    for (int mt = 0; mt < 2; mt++)
        ldsm_x4(aq[mt], sq + (uint32_t)(m0 + mt * 16 + a_row) * 48 + a_coloff);

    // per-row scales (rows r and r+8 of each m-tile)
    const int r = lane >> 2;
    float sc0[2], sc1[2];
#pragma unroll
    for (int mt = 0; mt < 2; mt++) {
        sc0[mt] = qsc_s[m0 + mt * 16 + r];
        sc1[mt] = qsc_s[m0 + mt * 16 + 8 + r];
    }

    // K B-frag lane addressing (non-trans x4: 16 keys x 16 dims)
    const int kb_row = ((lane >> 4) & 1) * 8 + (lane & 7);
    const int kb_coloff = ((lane >> 3) & 1) * 16;
    // V B-frag lane addressing (trans x4: 16 keys x 16 dims)
    const int vb_row = (lane & 7) + ((lane >> 3) & 1) * 8;
    const int vb_coloff = (lane >> 4) * 16;

    float oacc[2][2][4];
#pragma unroll
    for (int mt = 0; mt < 2; mt++)
#pragma unroll
        for (int nt = 0; nt < 2; nt++)
#pragma unroll
            for (int i = 0; i < 4; i++) oacc[mt][nt][i] = 0.f;
    float sumA[2] = {0.f, 0.f}, sumB[2] = {0.f, 0.f};

#pragma unroll 1
    for (int ch = 0; ch < 8; ch++) {
        const int K0 = ch * 32;

        // ---- QK^T for this 32-key chunk ----
        float cf[2][4][4];
#pragma unroll
        for (int mt = 0; mt < 2; mt++)
#pragma unroll
            for (int nt = 0; nt < 4; nt++)
#pragma unroll
                for (int i = 0; i < 4; i++) cf[mt][nt][i] = 0.f;

#pragma unroll
        for (int p = 0; p < 2; p++) {
            uint32_t bk[4];
            ldsm_x4(bk, sk + (uint32_t)(K0 + p * 16 + kb_row) * 48 + kb_coloff);
#pragma unroll
            for (int mt = 0; mt < 2; mt++) {
                mma16816(cf[mt][p * 2 + 0], aq[mt], &bk[0]);
                mma16816(cf[mt][p * 2 + 1], aq[mt], &bk[2]);
            }
        }

        // ---- softmax exp + pack to fp16 A-frags ----
        uint32_t aw[2][2][4];
#pragma unroll
        for (int nt = 0; nt < 4; nt++) {
            const int col = K0 + nt * 8 + (lane & 3) * 2;
            const float bi0 = bias_s[col];
            const float bi1 = bias_s[col + 1];
            const int ks = nt >> 1;
            const int hi = (nt & 1) * 2;
#pragma unroll
            for (int mt = 0; mt < 2; mt++) {
                const float w0 = ex2f(fmaf(cf[mt][nt][0], sc0[mt], bi0));
                const float w1 = ex2f(fmaf(cf[mt][nt][1], sc0[mt], bi1));
                const float w2 = ex2f(fmaf(cf[mt][nt][2], sc1[mt], bi0));
                const float w3 = ex2f(fmaf(cf[mt][nt][3], sc1[mt], bi1));
                sumA[mt] += w0 + w1;
                sumB[mt] += w2 + w3;
                __half2 p01 = __floats2half2_rn(w0, w1);
                __half2 p23 = __floats2half2_rn(w2, w3);
                aw[mt][ks][hi + 0] = *(uint32_t*)&p01;
                aw[mt][ks][hi + 1] = *(uint32_t*)&p23;
            }
        }

        // ---- P.V for this chunk ----
#pragma unroll
        for (int ks = 0; ks < 2; ks++) {
            uint32_t bv[4];
            ldsm_x4_t(bv, sv + (uint32_t)(K0 + ks * 16 + vb_row) * 48 + vb_coloff);
#pragma unroll
            for (int mt = 0; mt < 2; mt++) {
                mma16816(oacc[mt][0], aw[mt][ks], &bv[0]);
                mma16816(oacc[mt][1], aw[mt][ks], &bv[2]);
            }
        }
    }

    // ---- row-sum reduction across the 4-lane quad ----
#pragma unroll
    for (int mt = 0; mt < 2; mt++) {
        sumA[mt] += __shfl_xor_sync(0xffffffffu, sumA[mt], 1);
        sumA[mt] += __shfl_xor_sync(0xffffffffu, sumA[mt], 2);
        sumB[mt] += __shfl_xor_sync(0xffffffffu, sumB[mt], 1);
        sumB[mt] += __shfl_xor_sync(0xffffffffu, sumB[mt], 2);
    }
    const float invA0 = rcpf(sumA[0]), invB0 = rcpf(sumB[0]);
    const float invA1 = rcpf(sumA[1]), invB1 = rcpf(sumB[1]);

    // ---- store output (fp32) ----
    const long obase = (long)(b * S_) * D_ + c * H_;
#pragma unroll
    for (int mt = 0; mt < 2; mt++) {
        const float iA = mt ? invA1 : invA0;
        const float iB = mt ? invB1 : invB0;
#pragma unroll
        for (int nt = 0; nt < 2; nt++) {
            const int row = m0 + mt * 16 + r;
            const int col = nt * 8 + (lane & 3) * 2;
            float* p0 = out + obase + (long)row * D_ + col;
            float* p1 = p0 + 8 * D_;
            *(float2*)p0 = make_float2(oacc[mt][nt][0] * iA, oacc[mt][nt][1] * iA);
            *(float2*)p1 = make_float2(oacc[mt][nt][2] * iB, oacc[mt][nt][3] * iB);
        }
    }
}

// ---------------------------------------------------------------------------
extern "C" void kernel_launch(void* const* d_in, const int* in_sizes, int n_in,
                              void* d_out, int out_size)
{
    const float* x    = (const float*)d_in[0];
    const float* mask = (const float*)d_in[1];
    const float* Wq   = (const float*)d_in[2];
    const float* Wk   = (const float*)d_in[3];
    const float* Wv   = (const float*)d_in[4];
    float* out = (float*)d_out;

    __half *xh, *wh;
    cudaGetSymbolAddress((void**)&xh, g_xh);
    cudaGetSymbolAddress((void**)&wh, g_wh);

    cvt_x<<<(MTOT * D_ / 4 + 255) / 256, 256>>>(x, xh, MTOT * D_ / 4);
    dim3 gw((D_ * D_ / 4 + 255) / 256, 1, 3);
    cvt_w<<<gw, 256>>>(Wq, Wk, Wv, wh);

    static bool attr_set = false;
    if (!attr_set) {
        cudaFuncSetAttribute(qkv_tc, cudaFuncAttributeMaxDynamicSharedMemorySize, GEMM_SMEM);
        attr_set = true;
    }

    dim3 g1(D_ / GTN, MTOT / GTM, 3);
    qkv_tc<<<g1, 256, GEMM_SMEM>>>();

    dim3 g2(C_, B_);
    attn<<<g2, 256>>>(mask, out);
}